// round 2
// baseline (speedup 1.0000x reference)
#include <cuda_runtime.h>

#define FULLMASK 0xffffffffu

// 8-lane vector reduce: lane m (within its 8-lane group) ends with
// sum over the group's lanes of p[m]. 7 shuffles via halving butterfly.
__device__ __forceinline__ float reduce8_to_owner(const float p[8], int m) {
    bool h4 = (m & 4) != 0;
    float a0 = h4 ? p[4] : p[0], b0 = h4 ? p[0] : p[4];
    float a1 = h4 ? p[5] : p[1], b1 = h4 ? p[1] : p[5];
    float a2 = h4 ? p[6] : p[2], b2 = h4 ? p[2] : p[6];
    float a3 = h4 ? p[7] : p[3], b3 = h4 ? p[3] : p[7];
    a0 += __shfl_xor_sync(FULLMASK, b0, 4);
    a1 += __shfl_xor_sync(FULLMASK, b1, 4);
    a2 += __shfl_xor_sync(FULLMASK, b2, 4);
    a3 += __shfl_xor_sync(FULLMASK, b3, 4);
    bool h2 = (m & 2) != 0;
    float c0 = h2 ? a2 : a0, d0 = h2 ? a0 : a2;
    float c1 = h2 ? a3 : a1, d1 = h2 ? a1 : a3;
    c0 += __shfl_xor_sync(FULLMASK, d0, 2);
    c1 += __shfl_xor_sync(FULLMASK, d1, 2);
    bool h1 = (m & 1) != 0;
    float e0 = h1 ? c1 : c0, f0 = h1 ? c0 : c1;
    e0 += __shfl_xor_sync(FULLMASK, f0, 1);
    return e0;
}

// A = C1 P C2 for the star graph: A0[c] = row 0 of A, Ar[c] = rows>=1 (all equal).
// P given as 3 per-lane row-sets (rows m, m+8, 16[lane0 only]). C2r = row m of C2.
__device__ __forceinline__ void compute_A(
    const float Pa[8], const float Pb[8], const float Pc[8],
    const float C2r[8], int m, int base, bool lane0,
    float A0[8], float Ar[8])
{
    float sp[8], w[8];
    #pragma unroll
    for (int c = 0; c < 8; c++)
        sp[c] = (lane0 ? 0.f : Pa[c]) + Pb[c] + Pc[c]; // sum over rows n>=1
    float s_own = reduce8_to_owner(sp, m);             // s[m] at lane m
    #pragma unroll
    for (int l = 0; l < 8; l++) w[l] = s_own * C2r[l];
    float A0_own = reduce8_to_owner(w, m);             // A0[m] = sum_l s[l]*C2[l][m]
    #pragma unroll
    for (int c = 0; c < 8; c++) A0[c] = __shfl_sync(FULLMASK, A0_own, base + c);
    // distribute P row 0 (lane0's Pa): lane m gets P0[m]
    float p0_own = 0.f;
    #pragma unroll
    for (int l = 0; l < 8; l++) {
        float pv = __shfl_sync(FULLMASK, Pa[l], base);
        if (m == l) p0_own = pv;
    }
    #pragma unroll
    for (int l = 0; l < 8; l++) w[l] = p0_own * C2r[l];
    float Ar_own = reduce8_to_owner(w, m);
    #pragma unroll
    for (int c = 0; c < 8; c++) Ar[c] = __shfl_sync(FULLMASK, Ar_own, base + c);
}

__global__ void __launch_bounds__(128)
otgnn_fgw_kernel(const float* __restrict__ x,
                 const int* __restrict__ dst,      // edge_index row 1, [N*16]
                 const float* __restrict__ lt,     // latent_template [16][8][8]
                 const float* __restrict__ tf,     // templates_features [16][8][128]
                 const float* __restrict__ Wm,     // [16][8]
                 const float* __restrict__ bvec,   // [8]
                 float* __restrict__ out)          // [N][8]
{
    __shared__ float xls[17][128];
    __shared__ float Msh[16][17][8];
    __shared__ float xn2[17];
    __shared__ float fgw_s[16];

    const int node = blockIdx.x;
    const int tid  = threadIdx.x;
    const int t    = tid >> 3;      // template 0..15
    const int m    = tid & 7;       // lane within 8-group
    const int lane = tid & 31;
    const int base = lane & 24;     // first lane of the 8-group (within warp)
    const bool lane0 = (m == 0);

    // ---- Phase 0: gather local star features into smem ----
    #pragma unroll
    for (int r = 0; r < 17; r++) {
        int idx = (r == 0) ? node : __ldg(&dst[node * 16 + (r - 1)]);
        xls[r][tid] = __ldg(&x[idx * 128 + tid]);
    }
    __syncthreads();
    if (tid < 17) {
        float s = 0.f;
        #pragma unroll 8
        for (int c4 = 0; c4 < 32; c4++) {
            float4 v = *(const float4*)&xls[tid][c4 * 4];
            s += v.x*v.x + v.y*v.y + v.z*v.z + v.w*v.w;
        }
        xn2[tid] = s;
    }

    // ---- Phase 1: M[t][n][m] = (|x_n|^2 + |tf_tm|^2 - 2 x_n.tf_tm)/128 ----
    float acc[17];
    #pragma unroll
    for (int n = 0; n < 17; n++) acc[n] = 0.f;
    float tf2 = 0.f;
    const float4* tfr = (const float4*)(tf + (t * 8 + m) * 128);
    #pragma unroll 4
    for (int c4 = 0; c4 < 32; c4++) {
        float4 tv = __ldg(&tfr[c4]);
        tf2 += tv.x*tv.x + tv.y*tv.y + tv.z*tv.z + tv.w*tv.w;
        #pragma unroll
        for (int n = 0; n < 17; n++) {
            float4 xv = *(const float4*)&xls[n][c4 * 4];
            acc[n] += xv.x*tv.x + xv.y*tv.y + xv.z*tv.z + xv.w*tv.w;
        }
    }
    __syncthreads();   // xn2 ready
    #pragma unroll
    for (int n = 0; n < 17; n++)
        Msh[t][n][m] = (xn2[n] + tf2 - 2.f * acc[n]) * (1.f / 128.f);
    __syncthreads();

    // ---- Phase 2: FGW proximal loop, one (node,template) per 8-lane group ----
    float C2r[8];
    #pragma unroll
    for (int l = 0; l < 8; l++)
        C2r[l] = 0.5f * (__ldg(&lt[(t * 8 + m) * 8 + l]) + __ldg(&lt[(t * 8 + l) * 8 + m]));
    float cc2_own = 0.f;
    #pragma unroll
    for (int l = 0; l < 8; l++) cc2_own += C2r[l] * C2r[l];
    cc2_own *= 0.125f;                         // sum_l C2[m][l]^2 * p
    float cc2[8];
    #pragma unroll
    for (int c = 0; c < 8; c++) cc2[c] = __shfl_sync(FULLMASK, cc2_own, base + c);

    const float validC = lane0 ? 1.f : 0.f;                    // row 16 on lane 0 only
    const float c1hA = lane0 ? (16.f / 17.f) : (1.f / 17.f);   // (C1.^2 @ h)[row m]
    const float c1hX = 1.f / 17.f;                             // rows >= 1

    float Ka[8], Kb[8], Kc[8], vr[8];
    float u0 = 1.f, u1 = 1.f, u2 = 1.f;
    #pragma unroll
    for (int c = 0; c < 8; c++) {
        Ka[c] = 1.f / 136.f;              // initial P = h p
        Kb[c] = 1.f / 136.f;
        Kc[c] = validC * (1.f / 136.f);
        vr[c] = 1.f;
    }

    const float* Mrow_a = &Msh[t][m][0];
    const float* Mrow_b = &Msh[t][m + 8][0];
    const float* Mrow_c = &Msh[t][16][0];

    #pragma unroll 1
    for (int outer = 0; outer < 5; outer++) {
        float Pa[8], Pb[8], Pc[8];
        #pragma unroll
        for (int c = 0; c < 8; c++) {
            Pa[c] = u0 * Ka[c] * vr[c];
            Pb[c] = u1 * Kb[c] * vr[c];
            Pc[c] = u2 * Kc[c] * vr[c];   // 0 on lanes != 0
        }
        float A0[8], Ar[8];
        compute_A(Pa, Pb, Pc, C2r, m, base, lane0, A0, Ar);

        // grad = 0.5*(M + constC - 2A); gmin over the (17 x 8) tile
        float Ga[8], Gb[8], Gc[8];
        float gmin = 3.4e38f;
        #pragma unroll
        for (int c = 0; c < 8; c++) {
            float Aa = lane0 ? A0[c] : Ar[c];
            Ga[c] = 0.5f * (Mrow_a[c] + (c1hA + cc2[c] - 2.f * Aa));
            Gb[c] = 0.5f * (Mrow_b[c] + (c1hX + cc2[c] - 2.f * Ar[c]));
            Gc[c] = 0.5f * (Mrow_c[c] + (c1hX + cc2[c] - 2.f * Ar[c]));
            gmin = fminf(gmin, fminf(Ga[c], fminf(Gb[c], Gc[c])));
        }
        gmin = fminf(gmin, __shfl_xor_sync(FULLMASK, gmin, 1));
        gmin = fminf(gmin, __shfl_xor_sync(FULLMASK, gmin, 2));
        gmin = fminf(gmin, __shfl_xor_sync(FULLMASK, gmin, 4));

        // K = P * exp(-(grad - gmin)/EPS), EPS=0.2
        #pragma unroll
        for (int c = 0; c < 8; c++) {
            Ka[c] = Pa[c] * __expf((gmin - Ga[c]) * 5.f);
            Kb[c] = Pb[c] * __expf((gmin - Gb[c]) * 5.f);
            Kc[c] = Pc[c] * __expf((gmin - Gc[c]) * 5.f);
        }
        #pragma unroll
        for (int c = 0; c < 8; c++) vr[c] = 1.f;

        // Sinkhorn
        #pragma unroll 1
        for (int inner = 0; inner < 10; inner++) {
            float rs0 = 0.f, rs1 = 0.f, rs2 = 0.f;
            #pragma unroll
            for (int c = 0; c < 8; c++) {
                rs0 += Ka[c] * vr[c];
                rs1 += Kb[c] * vr[c];
                rs2 += Kc[c] * vr[c];
            }
            u0 = __fdividef(1.f / 17.f, rs0 + 1e-30f);
            u1 = __fdividef(1.f / 17.f, rs1 + 1e-30f);
            u2 = __fdividef(1.f / 17.f, rs2 + 1e-30f);  // finite junk on lanes!=0; K=0 kills it
            float part[8];
            #pragma unroll
            for (int c = 0; c < 8; c++)
                part[c] = Ka[c] * u0 + Kb[c] * u1 + Kc[c] * u2;
            float cs_own = reduce8_to_owner(part, m);
            float v_own = __fdividef(0.125f, cs_own + 1e-30f);
            #pragma unroll
            for (int c = 0; c < 8; c++) vr[c] = __shfl_sync(FULLMASK, v_own, base + c);
        }
    }

    // ---- Final: fgw = 0.5 * sum((M + constC - 2 A(P)) .* P) ----
    float Pa[8], Pb[8], Pc[8];
    #pragma unroll
    for (int c = 0; c < 8; c++) {
        Pa[c] = u0 * Ka[c] * vr[c];
        Pb[c] = u1 * Kb[c] * vr[c];
        Pc[c] = u2 * Kc[c] * vr[c];
    }
    float A0[8], Ar[8];
    compute_A(Pa, Pb, Pc, C2r, m, base, lane0, A0, Ar);
    float loc = 0.f;
    #pragma unroll
    for (int c = 0; c < 8; c++) {
        float Aa = lane0 ? A0[c] : Ar[c];
        loc += (0.5f * (Mrow_a[c] + (c1hA + cc2[c] - 2.f * Aa))) * Pa[c];
        loc += (0.5f * (Mrow_b[c] + (c1hX + cc2[c] - 2.f * Ar[c]))) * Pb[c];
        loc += (0.5f * (Mrow_c[c] + (c1hX + cc2[c] - 2.f * Ar[c]))) * Pc[c];
    }
    loc += __shfl_xor_sync(FULLMASK, loc, 1);
    loc += __shfl_xor_sync(FULLMASK, loc, 2);
    loc += __shfl_xor_sync(FULLMASK, loc, 4);
    if (lane0) fgw_s[t] = loc;
    __syncthreads();

    // ---- Output: out[node] = fgw @ W + b  (8 classes) ----
    if (tid < 8) {
        float o = __ldg(&bvec[tid]);
        #pragma unroll
        for (int tt = 0; tt < 16; tt++)
            o += fgw_s[tt] * __ldg(&Wm[tt * 8 + tid]);
        out[node * 8 + tid] = o;
    }
}

extern "C" void kernel_launch(void* const* d_in, const int* in_sizes, int n_in,
                              void* d_out, int out_size) {
    const float* x   = (const float*)d_in[0];
    const int*   ei  = (const int*)d_in[1];       // [2, N*16]
    const float* lt  = (const float*)d_in[2];     // [16,8,8]
    const float* tf  = (const float*)d_in[3];     // [16,8,128]
    const float* Wm  = (const float*)d_in[4];     // [16,8]
    const float* bv  = (const float*)d_in[5];     // [8]
    float* out = (float*)d_out;

    const int N = in_sizes[0] / 128;
    const int* dst = ei + N * 16;                 // row 1 of edge_index

    otgnn_fgw_kernel<<<N, 128>>>(x, dst, lt, tf, Wm, bv, out);
}

// round 3
// speedup vs baseline: 2.3722x; 2.3722x over previous
#include <cuda_runtime.h>

#define FULLMASK 0xffffffffu
#define MAXN 16384

// Scratch (device globals — no allocation)
__device__ float g_G[MAXN * 128];   // G[j][tm] = x_j . tf_{t,m}
__device__ float g_xn2[MAXN];       // |x_j|^2
__device__ float g_tf2[128];        // |tf_{t,m}|^2
__device__ float g_C2s[128 * 8];    // symmetrized C2 row: C2s[t*8+m][l]

// ---------------- Kernel A: precompute G, xn2, tf2, C2sym ----------------
__global__ void __launch_bounds__(128)
precompute_kernel(const float* __restrict__ x,
                  const float* __restrict__ lt,
                  const float* __restrict__ tf,
                  int N)
{
    __shared__ float xs[4][128];
    __shared__ float part[4][4];

    const int tid = threadIdx.x;
    const int n0  = blockIdx.x * 4;
    const int wid = tid >> 5, lane = tid & 31;

    #pragma unroll
    for (int j = 0; j < 4; j++) {
        int node = n0 + j;
        xs[j][tid] = (node < N) ? __ldg(&x[node * 128 + tid]) : 0.f;
    }
    __syncthreads();

    const float4* tfr = (const float4*)(tf + tid * 128);
    float acc0 = 0.f, acc1 = 0.f, acc2 = 0.f, acc3 = 0.f, tf2a = 0.f;
    #pragma unroll 8
    for (int c4 = 0; c4 < 32; c4++) {
        float4 tv = __ldg(&tfr[c4]);
        tf2a += tv.x*tv.x + tv.y*tv.y + tv.z*tv.z + tv.w*tv.w;
        float4 v0 = *(const float4*)&xs[0][c4 * 4];
        float4 v1 = *(const float4*)&xs[1][c4 * 4];
        float4 v2 = *(const float4*)&xs[2][c4 * 4];
        float4 v3 = *(const float4*)&xs[3][c4 * 4];
        acc0 += v0.x*tv.x + v0.y*tv.y + v0.z*tv.z + v0.w*tv.w;
        acc1 += v1.x*tv.x + v1.y*tv.y + v1.z*tv.z + v1.w*tv.w;
        acc2 += v2.x*tv.x + v2.y*tv.y + v2.z*tv.z + v2.w*tv.w;
        acc3 += v3.x*tv.x + v3.y*tv.y + v3.z*tv.z + v3.w*tv.w;
    }
    if (n0 + 0 < N) g_G[(n0 + 0) * 128 + tid] = acc0;
    if (n0 + 1 < N) g_G[(n0 + 1) * 128 + tid] = acc1;
    if (n0 + 2 < N) g_G[(n0 + 2) * 128 + tid] = acc2;
    if (n0 + 3 < N) g_G[(n0 + 3) * 128 + tid] = acc3;

    // xn2 for the 4 nodes
    #pragma unroll
    for (int j = 0; j < 4; j++) {
        float v = xs[j][tid];
        float s = v * v;
        #pragma unroll
        for (int d = 16; d >= 1; d >>= 1) s += __shfl_xor_sync(FULLMASK, s, d);
        if (lane == 0) part[j][wid] = s;
    }
    __syncthreads();
    if (tid < 4 && n0 + tid < N)
        g_xn2[n0 + tid] = part[tid][0] + part[tid][1] + part[tid][2] + part[tid][3];

    if (blockIdx.x == 0) {
        g_tf2[tid] = tf2a;
        const int t = tid >> 3, m = tid & 7;
        #pragma unroll
        for (int l = 0; l < 8; l++)
            g_C2s[tid * 8 + l] = 0.5f * (__ldg(&lt[(t * 8 + m) * 8 + l]) +
                                         __ldg(&lt[(t * 8 + l) * 8 + m]));
    }
}

// 8-lane vector reduce: lane m (within its 8-lane group) ends with
// sum over the group's lanes of p[m]. 7 shuffles via halving butterfly.
__device__ __forceinline__ float reduce8_to_owner(const float p[8], int m) {
    bool h4 = (m & 4) != 0;
    float a0 = h4 ? p[4] : p[0], b0 = h4 ? p[0] : p[4];
    float a1 = h4 ? p[5] : p[1], b1 = h4 ? p[1] : p[5];
    float a2 = h4 ? p[6] : p[2], b2 = h4 ? p[2] : p[6];
    float a3 = h4 ? p[7] : p[3], b3 = h4 ? p[3] : p[7];
    a0 += __shfl_xor_sync(FULLMASK, b0, 4);
    a1 += __shfl_xor_sync(FULLMASK, b1, 4);
    a2 += __shfl_xor_sync(FULLMASK, b2, 4);
    a3 += __shfl_xor_sync(FULLMASK, b3, 4);
    bool h2 = (m & 2) != 0;
    float c0 = h2 ? a2 : a0, d0 = h2 ? a0 : a2;
    float c1 = h2 ? a3 : a1, d1 = h2 ? a1 : a3;
    c0 += __shfl_xor_sync(FULLMASK, d0, 2);
    c1 += __shfl_xor_sync(FULLMASK, d1, 2);
    bool h1 = (m & 1) != 0;
    float e0 = h1 ? c1 : c0, f0 = h1 ? c0 : c1;
    e0 += __shfl_xor_sync(FULLMASK, f0, 1);
    return e0;
}

// A = C1 P C2 for the star graph.
__device__ __forceinline__ void compute_A(
    const float Pa[8], const float Pb[8], const float Pc[8],
    const float C2r[8], int m, int base, bool lane0,
    float A0[8], float Ar[8])
{
    float sp[8], w[8];
    #pragma unroll
    for (int c = 0; c < 8; c++)
        sp[c] = (lane0 ? 0.f : Pa[c]) + Pb[c] + Pc[c];
    float s_own = reduce8_to_owner(sp, m);
    #pragma unroll
    for (int l = 0; l < 8; l++) w[l] = s_own * C2r[l];
    float A0_own = reduce8_to_owner(w, m);
    #pragma unroll
    for (int c = 0; c < 8; c++) A0[c] = __shfl_sync(FULLMASK, A0_own, base + c);
    float p0_own = 0.f;
    #pragma unroll
    for (int l = 0; l < 8; l++) {
        float pv = __shfl_sync(FULLMASK, Pa[l], base);
        if (m == l) p0_own = pv;
    }
    #pragma unroll
    for (int l = 0; l < 8; l++) w[l] = p0_own * C2r[l];
    float Ar_own = reduce8_to_owner(w, m);
    #pragma unroll
    for (int c = 0; c < 8; c++) Ar[c] = __shfl_sync(FULLMASK, Ar_own, base + c);
}

// ---------------- Kernel B: FGW per (node) ----------------
__global__ void __launch_bounds__(128)
otgnn_fgw_kernel(const int* __restrict__ dst,
                 const float* __restrict__ Wm,
                 const float* __restrict__ bvec,
                 float* __restrict__ out)
{
    __shared__ int   idxs[17];
    __shared__ float xn2s[17];
    __shared__ float fgw_s[16];

    const int node = blockIdx.x;
    const int tid  = threadIdx.x;
    const int t    = tid >> 3;
    const int m    = tid & 7;
    const int lane = tid & 31;
    const int base = lane & 24;
    const bool lane0 = (m == 0);

    if (tid < 17) {
        int id = (tid == 0) ? node : __ldg(&dst[node * 16 + tid - 1]);
        idxs[tid] = id;
        xn2s[tid] = g_xn2[id];
    }
    __syncthreads();

    // ---- Build M rows directly in registers from precomputed G ----
    float tf2c[8];
    {
        float4 a = *(const float4*)&g_tf2[t * 8];
        float4 b = *(const float4*)&g_tf2[t * 8 + 4];
        tf2c[0]=a.x; tf2c[1]=a.y; tf2c[2]=a.z; tf2c[3]=a.w;
        tf2c[4]=b.x; tf2c[5]=b.y; tf2c[6]=b.z; tf2c[7]=b.w;
    }
    float Ma[8], Mb[8], Mc[8];
    {
        const int ia = idxs[m], ib = idxs[m + 8], ic = idxs[16];
        const float na = xn2s[m], nb = xn2s[m + 8], nc = xn2s[16];
        float4 a0 = *(const float4*)&g_G[ia * 128 + t * 8];
        float4 a1 = *(const float4*)&g_G[ia * 128 + t * 8 + 4];
        float4 b0 = *(const float4*)&g_G[ib * 128 + t * 8];
        float4 b1 = *(const float4*)&g_G[ib * 128 + t * 8 + 4];
        float4 c0 = *(const float4*)&g_G[ic * 128 + t * 8];
        float4 c1 = *(const float4*)&g_G[ic * 128 + t * 8 + 4];
        const float ga[8] = {a0.x,a0.y,a0.z,a0.w,a1.x,a1.y,a1.z,a1.w};
        const float gb[8] = {b0.x,b0.y,b0.z,b0.w,b1.x,b1.y,b1.z,b1.w};
        const float gc[8] = {c0.x,c0.y,c0.z,c0.w,c1.x,c1.y,c1.z,c1.w};
        #pragma unroll
        for (int c = 0; c < 8; c++) {
            Ma[c] = (na + tf2c[c] - 2.f * ga[c]) * (1.f / 128.f);
            Mb[c] = (nb + tf2c[c] - 2.f * gb[c]) * (1.f / 128.f);
            Mc[c] = (nc + tf2c[c] - 2.f * gc[c]) * (1.f / 128.f);
        }
    }

    // ---- C2 row + constC pieces ----
    float C2r[8];
    {
        float4 a = *(const float4*)&g_C2s[tid * 8];
        float4 b = *(const float4*)&g_C2s[tid * 8 + 4];
        C2r[0]=a.x; C2r[1]=a.y; C2r[2]=a.z; C2r[3]=a.w;
        C2r[4]=b.x; C2r[5]=b.y; C2r[6]=b.z; C2r[7]=b.w;
    }
    float cc2_own = 0.f;
    #pragma unroll
    for (int l = 0; l < 8; l++) cc2_own += C2r[l] * C2r[l];
    cc2_own *= 0.125f;
    float cc2[8];
    #pragma unroll
    for (int c = 0; c < 8; c++) cc2[c] = __shfl_sync(FULLMASK, cc2_own, base + c);

    const float validC = lane0 ? 1.f : 0.f;
    const float c1hA = lane0 ? (16.f / 17.f) : (1.f / 17.f);
    const float c1hX = 1.f / 17.f;

    float Ka[8], Kb[8], Kc[8], vr[8];
    float u0 = 1.f, u1 = 1.f, u2 = 1.f;
    #pragma unroll
    for (int c = 0; c < 8; c++) {
        Ka[c] = 1.f / 136.f;
        Kb[c] = 1.f / 136.f;
        Kc[c] = validC * (1.f / 136.f);
        vr[c] = 1.f;
    }

    #pragma unroll 1
    for (int outer = 0; outer < 5; outer++) {
        float Pa[8], Pb[8], Pc[8];
        #pragma unroll
        for (int c = 0; c < 8; c++) {
            Pa[c] = u0 * Ka[c] * vr[c];
            Pb[c] = u1 * Kb[c] * vr[c];
            Pc[c] = u2 * Kc[c] * vr[c];
        }
        float A0[8], Ar[8];
        compute_A(Pa, Pb, Pc, C2r, m, base, lane0, A0, Ar);

        float Ga[8], Gb[8], Gc[8];
        float gmin = 3.4e38f;
        #pragma unroll
        for (int c = 0; c < 8; c++) {
            float Aa = lane0 ? A0[c] : Ar[c];
            Ga[c] = 0.5f * (Ma[c] + (c1hA + cc2[c] - 2.f * Aa));
            Gb[c] = 0.5f * (Mb[c] + (c1hX + cc2[c] - 2.f * Ar[c]));
            Gc[c] = 0.5f * (Mc[c] + (c1hX + cc2[c] - 2.f * Ar[c]));
            gmin = fminf(gmin, fminf(Ga[c], fminf(Gb[c], Gc[c])));
        }
        gmin = fminf(gmin, __shfl_xor_sync(FULLMASK, gmin, 1));
        gmin = fminf(gmin, __shfl_xor_sync(FULLMASK, gmin, 2));
        gmin = fminf(gmin, __shfl_xor_sync(FULLMASK, gmin, 4));

        #pragma unroll
        for (int c = 0; c < 8; c++) {
            Ka[c] = Pa[c] * __expf((gmin - Ga[c]) * 5.f);
            Kb[c] = Pb[c] * __expf((gmin - Gb[c]) * 5.f);
            Kc[c] = Pc[c] * __expf((gmin - Gc[c]) * 5.f);
        }
        #pragma unroll
        for (int c = 0; c < 8; c++) vr[c] = 1.f;

        #pragma unroll 1
        for (int inner = 0; inner < 10; inner++) {
            float rs0 = 0.f, rs1 = 0.f, rs2 = 0.f;
            #pragma unroll
            for (int c = 0; c < 8; c++) {
                rs0 += Ka[c] * vr[c];
                rs1 += Kb[c] * vr[c];
                rs2 += Kc[c] * vr[c];
            }
            u0 = __fdividef(1.f / 17.f, rs0 + 1e-30f);
            u1 = __fdividef(1.f / 17.f, rs1 + 1e-30f);
            u2 = __fdividef(1.f / 17.f, rs2 + 1e-30f);
            float part[8];
            #pragma unroll
            for (int c = 0; c < 8; c++)
                part[c] = Ka[c] * u0 + Kb[c] * u1 + Kc[c] * u2;
            float cs_own = reduce8_to_owner(part, m);
            float v_own = __fdividef(0.125f, cs_own + 1e-30f);
            #pragma unroll
            for (int c = 0; c < 8; c++) vr[c] = __shfl_sync(FULLMASK, v_own, base + c);
        }
    }

    // ---- Final fgw ----
    float Pa[8], Pb[8], Pc[8];
    #pragma unroll
    for (int c = 0; c < 8; c++) {
        Pa[c] = u0 * Ka[c] * vr[c];
        Pb[c] = u1 * Kb[c] * vr[c];
        Pc[c] = u2 * Kc[c] * vr[c];
    }
    float A0[8], Ar[8];
    compute_A(Pa, Pb, Pc, C2r, m, base, lane0, A0, Ar);
    float loc = 0.f;
    #pragma unroll
    for (int c = 0; c < 8; c++) {
        float Aa = lane0 ? A0[c] : Ar[c];
        loc += (0.5f * (Ma[c] + (c1hA + cc2[c] - 2.f * Aa))) * Pa[c];
        loc += (0.5f * (Mb[c] + (c1hX + cc2[c] - 2.f * Ar[c]))) * Pb[c];
        loc += (0.5f * (Mc[c] + (c1hX + cc2[c] - 2.f * Ar[c]))) * Pc[c];
    }
    loc += __shfl_xor_sync(FULLMASK, loc, 1);
    loc += __shfl_xor_sync(FULLMASK, loc, 2);
    loc += __shfl_xor_sync(FULLMASK, loc, 4);
    if (lane0) fgw_s[t] = loc;
    __syncthreads();

    if (tid < 8) {
        float o = __ldg(&bvec[tid]);
        #pragma unroll
        for (int tt = 0; tt < 16; tt++)
            o += fgw_s[tt] * __ldg(&Wm[tt * 8 + tid]);
        out[node * 8 + tid] = o;
    }
}

extern "C" void kernel_launch(void* const* d_in, const int* in_sizes, int n_in,
                              void* d_out, int out_size) {
    const float* x   = (const float*)d_in[0];
    const int*   ei  = (const int*)d_in[1];       // [2, N*16]
    const float* lt  = (const float*)d_in[2];     // [16,8,8]
    const float* tf  = (const float*)d_in[3];     // [16,8,128]
    const float* Wm  = (const float*)d_in[4];     // [16,8]
    const float* bv  = (const float*)d_in[5];     // [8]
    float* out = (float*)d_out;

    const int N = in_sizes[0] / 128;
    const int* dst = ei + N * 16;                 // row 1 of edge_index

    precompute_kernel<<<(N + 3) / 4, 128>>>(x, lt, tf, N);
    otgnn_fgw_kernel<<<N, 128>>>(dst, Wm, bv, out);
}

// round 4
// speedup vs baseline: 3.0359x; 1.2798x over previous
#include <cuda_runtime.h>

#define FULLMASK 0xffffffffu
#define MAXN 16384

// Scratch (device globals — no allocation)
__device__ float g_G[MAXN * 128];   // G[j][tm] = x_j . tf_{t,m}
__device__ float g_xn2[MAXN];       // |x_j|^2
__device__ float g_tf2[128];        // |tf_{t,m}|^2
__device__ float g_C2s[128 * 8];    // symmetrized C2 row

// ---------------- packed f32x2 helpers (sm_103a FFMA2 path) ----------------
union f2u { float2 f; unsigned long long u; };
__device__ __forceinline__ float2 fma2(float2 a, float2 b, float2 c) {
    f2u A, B, C, D; A.f = a; B.f = b; C.f = c;
    asm("fma.rn.f32x2 %0, %1, %2, %3;" : "=l"(D.u) : "l"(A.u), "l"(B.u), "l"(C.u));
    return D.f;
}
__device__ __forceinline__ float2 mul2(float2 a, float2 b) {
    f2u A, B, D; A.f = a; B.f = b;
    asm("mul.rn.f32x2 %0, %1, %2;" : "=l"(D.u) : "l"(A.u), "l"(B.u));
    return D.f;
}
__device__ __forceinline__ float2 add2(float2 a, float2 b) {
    f2u A, B, D; A.f = a; B.f = b;
    asm("add.rn.f32x2 %0, %1, %2;" : "=l"(D.u) : "l"(A.u), "l"(B.u));
    return D.f;
}
__device__ __forceinline__ float ex2(float x) {
    float r; asm("ex2.approx.f32 %0, %1;" : "=f"(r) : "f"(x)); return r;
}

// ---------------- Kernel A: precompute G, xn2, tf2, C2sym ----------------
__global__ void __launch_bounds__(128)
precompute_kernel(const float* __restrict__ x,
                  const float* __restrict__ lt,
                  const float* __restrict__ tf,
                  int N)
{
    __shared__ float xs[8][128];
    const int tid = threadIdx.x;
    const int n0  = blockIdx.x * 8;

    #pragma unroll
    for (int j = 0; j < 8; j++) {
        int node = n0 + j;
        xs[j][tid] = (node < N) ? __ldg(&x[node * 128 + tid]) : 0.f;
    }
    __syncthreads();

    const float4* tfr = (const float4*)(tf + tid * 128);
    float acc[8];
    #pragma unroll
    for (int j = 0; j < 8; j++) acc[j] = 0.f;
    float tf2a = 0.f;
    #pragma unroll 4
    for (int c4 = 0; c4 < 32; c4++) {
        float4 tv = __ldg(&tfr[c4]);
        tf2a += tv.x*tv.x + tv.y*tv.y + tv.z*tv.z + tv.w*tv.w;
        #pragma unroll
        for (int j = 0; j < 8; j++) {
            float4 v = *(const float4*)&xs[j][c4 * 4];
            acc[j] += v.x*tv.x + v.y*tv.y + v.z*tv.z + v.w*tv.w;
        }
    }
    #pragma unroll
    for (int j = 0; j < 8; j++)
        if (n0 + j < N) g_G[(n0 + j) * 128 + tid] = acc[j];

    // xn2: node jn handled by 16 threads
    const int jn = tid >> 4, off = (tid & 15) * 8;
    float s = 0.f;
    #pragma unroll
    for (int k = 0; k < 8; k++) { float v = xs[jn][off + k]; s += v * v; }
    s += __shfl_xor_sync(FULLMASK, s, 1);
    s += __shfl_xor_sync(FULLMASK, s, 2);
    s += __shfl_xor_sync(FULLMASK, s, 4);
    s += __shfl_xor_sync(FULLMASK, s, 8);
    if ((tid & 15) == 0 && n0 + jn < N) g_xn2[n0 + jn] = s;

    if (blockIdx.x == 0) {
        g_tf2[tid] = tf2a;
        const int t = tid >> 3, m = tid & 7;
        #pragma unroll
        for (int l = 0; l < 8; l++)
            g_C2s[tid * 8 + l] = 0.5f * (__ldg(&lt[(t * 8 + m) * 8 + l]) +
                                         __ldg(&lt[(t * 8 + l) * 8 + m]));
    }
}

// 8-lane reduce on packed vector: lane m ends with sum over group lanes of
// element m. q = elements 0..7 as 4 float2 pairs. 7 SHFL + packed adds.
__device__ __forceinline__ float reduce8_to_owner2(const float2 q[4], int m) {
    bool h4 = (m & 4) != 0;
    float2 a0 = h4 ? q[2] : q[0], b0 = h4 ? q[0] : q[2];
    float2 a1 = h4 ? q[3] : q[1], b1 = h4 ? q[1] : q[3];
    b0.x = __shfl_xor_sync(FULLMASK, b0.x, 4);
    b0.y = __shfl_xor_sync(FULLMASK, b0.y, 4);
    b1.x = __shfl_xor_sync(FULLMASK, b1.x, 4);
    b1.y = __shfl_xor_sync(FULLMASK, b1.y, 4);
    a0 = add2(a0, b0); a1 = add2(a1, b1);
    bool h2 = (m & 2) != 0;
    float2 c0 = h2 ? a1 : a0, d0 = h2 ? a0 : a1;
    d0.x = __shfl_xor_sync(FULLMASK, d0.x, 2);
    d0.y = __shfl_xor_sync(FULLMASK, d0.y, 2);
    c0 = add2(c0, d0);
    bool h1 = (m & 1) != 0;
    float e = h1 ? c0.y : c0.x, f = h1 ? c0.x : c0.y;
    e += __shfl_xor_sync(FULLMASK, f, 1);
    return e;
}

// -A = -(C1 P C2) for the star graph (negated so grad = Mh + nA).
__device__ __forceinline__ void compute_nA2(
    const float2 Pa[4], const float2 Pb[4], const float2 Pc[4],
    const float2 C2r[4], int m, int base, bool lane0,
    float2 nA0[4], float2 nAr[4])
{
    float2 sp[4], w[4];
    #pragma unroll
    for (int c = 0; c < 4; c++) {
        float2 t = lane0 ? make_float2(0.f, 0.f) : Pa[c];
        sp[c] = add2(add2(t, Pb[c]), Pc[c]);
    }
    float s_own = -reduce8_to_owner2(sp, m);
    float2 ss = make_float2(s_own, s_own);
    #pragma unroll
    for (int c = 0; c < 4; c++) w[c] = mul2(C2r[c], ss);
    float nA0_own = reduce8_to_owner2(w, m);
    #pragma unroll
    for (int c = 0; c < 4; c++) {
        nA0[c].x = __shfl_sync(FULLMASK, nA0_own, base + 2 * c);
        nA0[c].y = __shfl_sync(FULLMASK, nA0_own, base + 2 * c + 1);
    }
    // distribute P row 0 (lane base's Pa): lane m gets P0[m]
    float p0_own = 0.f;
    #pragma unroll
    for (int l = 0; l < 4; l++) {
        float px = __shfl_sync(FULLMASK, Pa[l].x, base);
        float py = __shfl_sync(FULLMASK, Pa[l].y, base);
        if (m == 2 * l)     p0_own = px;
        if (m == 2 * l + 1) p0_own = py;
    }
    float2 pp = make_float2(-p0_own, -p0_own);
    #pragma unroll
    for (int c = 0; c < 4; c++) w[c] = mul2(C2r[c], pp);
    float nAr_own = reduce8_to_owner2(w, m);
    #pragma unroll
    for (int c = 0; c < 4; c++) {
        nAr[c].x = __shfl_sync(FULLMASK, nAr_own, base + 2 * c);
        nAr[c].y = __shfl_sync(FULLMASK, nAr_own, base + 2 * c + 1);
    }
}

// ---------------- Kernel B: FGW per node ----------------
__global__ void __launch_bounds__(128)
otgnn_fgw_kernel(const int* __restrict__ dst,
                 const float* __restrict__ Wm,
                 const float* __restrict__ bvec,
                 float* __restrict__ out)
{
    __shared__ int   idxs[17];
    __shared__ float xn2s[17];
    __shared__ float fgw_s[16];

    const int node = blockIdx.x;
    const int tid  = threadIdx.x;
    const int t    = tid >> 3;
    const int m    = tid & 7;
    const int lane = tid & 31;
    const int base = lane & 24;
    const bool lane0 = (m == 0);

    if (tid < 17) {
        int id = (tid == 0) ? node : __ldg(&dst[node * 16 + tid - 1]);
        idxs[tid] = id;
        xn2s[tid] = g_xn2[id];
    }
    __syncthreads();

    // ---- C2 row + cc2 broadcast ----
    float2 C2r[4];
    {
        float4 a = *(const float4*)&g_C2s[tid * 8];
        float4 b = *(const float4*)&g_C2s[tid * 8 + 4];
        C2r[0] = make_float2(a.x, a.y); C2r[1] = make_float2(a.z, a.w);
        C2r[2] = make_float2(b.x, b.y); C2r[3] = make_float2(b.z, b.w);
    }
    float cc2_own = 0.f;
    #pragma unroll
    for (int c = 0; c < 4; c++)
        cc2_own += C2r[c].x * C2r[c].x + C2r[c].y * C2r[c].y;
    cc2_own *= 0.125f;
    float cc2v[8];
    #pragma unroll
    for (int c = 0; c < 8; c++) cc2v[c] = __shfl_sync(FULLMASK, cc2_own, base + c);

    const float c1hA = lane0 ? (16.f / 17.f) : (1.f / 17.f);
    const float c1hX = 1.f / 17.f;

    // ---- Mh = 0.5*(M + c1h + cc2), packed, loop-invariant ----
    float2 Mah[4], Mbh[4], Mch[4];
    {
        float tf2c[8];
        float4 a = *(const float4*)&g_tf2[t * 8];
        float4 b = *(const float4*)&g_tf2[t * 8 + 4];
        tf2c[0]=a.x; tf2c[1]=a.y; tf2c[2]=a.z; tf2c[3]=a.w;
        tf2c[4]=b.x; tf2c[5]=b.y; tf2c[6]=b.z; tf2c[7]=b.w;
        const int ia = idxs[m], ib = idxs[m + 8], ic = idxs[16];
        const float na = xn2s[m], nb = xn2s[m + 8], nc = xn2s[16];
        float4 a0 = *(const float4*)&g_G[ia * 128 + t * 8];
        float4 a1 = *(const float4*)&g_G[ia * 128 + t * 8 + 4];
        float4 b0 = *(const float4*)&g_G[ib * 128 + t * 8];
        float4 b1 = *(const float4*)&g_G[ib * 128 + t * 8 + 4];
        float4 c0 = *(const float4*)&g_G[ic * 128 + t * 8];
        float4 c1 = *(const float4*)&g_G[ic * 128 + t * 8 + 4];
        const float ga[8] = {a0.x,a0.y,a0.z,a0.w,a1.x,a1.y,a1.z,a1.w};
        const float gb[8] = {b0.x,b0.y,b0.z,b0.w,b1.x,b1.y,b1.z,b1.w};
        const float gc[8] = {c0.x,c0.y,c0.z,c0.w,c1.x,c1.y,c1.z,c1.w};
        float ta[8], tb[8], tc[8];
        #pragma unroll
        for (int c = 0; c < 8; c++) {
            float Ma = (na + tf2c[c] - 2.f * ga[c]) * (1.f / 128.f);
            float Mb = (nb + tf2c[c] - 2.f * gb[c]) * (1.f / 128.f);
            float Mc = (nc + tf2c[c] - 2.f * gc[c]) * (1.f / 128.f);
            ta[c] = 0.5f * (Ma + c1hA + cc2v[c]);
            tb[c] = 0.5f * (Mb + c1hX + cc2v[c]);
            tc[c] = 0.5f * (Mc + c1hX + cc2v[c]);
        }
        #pragma unroll
        for (int c = 0; c < 4; c++) {
            Mah[c] = make_float2(ta[2*c], ta[2*c+1]);
            Mbh[c] = make_float2(tb[2*c], tb[2*c+1]);
            Mch[c] = make_float2(tc[2*c], tc[2*c+1]);
        }
    }

    const float validC = lane0 ? 1.f : 0.f;
    float2 Ka2[4], Kb2[4], Kc2[4], vr2[4];
    float u0 = 1.f, u1 = 1.f, u2 = 1.f;
    #pragma unroll
    for (int c = 0; c < 4; c++) {
        Ka2[c] = make_float2(1.f/136.f, 1.f/136.f);
        Kb2[c] = make_float2(1.f/136.f, 1.f/136.f);
        Kc2[c] = make_float2(validC/136.f, validC/136.f);
        vr2[c] = make_float2(1.f, 1.f);
    }

    const float EKC = 7.21347520444482f;  // 5 * log2(e)

    #pragma unroll 1
    for (int outer = 0; outer < 5; outer++) {
        float2 uu0 = make_float2(u0,u0), uu1 = make_float2(u1,u1), uu2 = make_float2(u2,u2);
        float2 Pa2[4], Pb2[4], Pc2[4];
        #pragma unroll
        for (int c = 0; c < 4; c++) {
            Pa2[c] = mul2(mul2(Ka2[c], vr2[c]), uu0);
            Pb2[c] = mul2(mul2(Kb2[c], vr2[c]), uu1);
            Pc2[c] = mul2(mul2(Kc2[c], vr2[c]), uu2);
        }
        float2 nA0[4], nAr[4];
        compute_nA2(Pa2, Pb2, Pc2, C2r, m, base, lane0, nA0, nAr);

        float2 Ga2[4], Gb2[4], Gc2[4];
        float gmin = 3.4e38f;
        #pragma unroll
        for (int c = 0; c < 4; c++) {
            float2 nAa = lane0 ? nA0[c] : nAr[c];
            Ga2[c] = add2(Mah[c], nAa);
            Gb2[c] = add2(Mbh[c], nAr[c]);
            Gc2[c] = add2(Mch[c], nAr[c]);
            gmin = fminf(gmin, fminf(fminf(Ga2[c].x, Ga2[c].y),
                          fminf(fminf(Gb2[c].x, Gb2[c].y),
                                fminf(Gc2[c].x, Gc2[c].y))));
        }
        gmin = fminf(gmin, __shfl_xor_sync(FULLMASK, gmin, 1));
        gmin = fminf(gmin, __shfl_xor_sync(FULLMASK, gmin, 2));
        gmin = fminf(gmin, __shfl_xor_sync(FULLMASK, gmin, 4));

        float2 gk2 = make_float2(gmin * EKC, gmin * EKC);
        float2 nk2 = make_float2(-EKC, -EKC);
        #pragma unroll
        for (int c = 0; c < 4; c++) {
            float2 e;
            e = fma2(Ga2[c], nk2, gk2); e.x = ex2(e.x); e.y = ex2(e.y);
            Ka2[c] = mul2(Pa2[c], e);
            e = fma2(Gb2[c], nk2, gk2); e.x = ex2(e.x); e.y = ex2(e.y);
            Kb2[c] = mul2(Pb2[c], e);
            e = fma2(Gc2[c], nk2, gk2); e.x = ex2(e.x); e.y = ex2(e.y);
            Kc2[c] = mul2(Pc2[c], e);
            vr2[c] = make_float2(1.f, 1.f);
        }

        #pragma unroll 1
        for (int inner = 0; inner < 10; inner++) {
            float2 r0 = make_float2(0.f,0.f), r1 = r0, r2 = r0;
            #pragma unroll
            for (int c = 0; c < 4; c++) {
                r0 = fma2(Ka2[c], vr2[c], r0);
                r1 = fma2(Kb2[c], vr2[c], r1);
                r2 = fma2(Kc2[c], vr2[c], r2);
            }
            u0 = __fdividef(1.f / 17.f, r0.x + r0.y + 1e-30f);
            u1 = __fdividef(1.f / 17.f, r1.x + r1.y + 1e-30f);
            u2 = __fdividef(1.f / 17.f, r2.x + r2.y + 1e-30f);
            float2 w0 = make_float2(u0,u0), w1 = make_float2(u1,u1), w2 = make_float2(u2,u2);
            float2 part2[4];
            #pragma unroll
            for (int c = 0; c < 4; c++)
                part2[c] = fma2(Kc2[c], w2, fma2(Kb2[c], w1, mul2(Ka2[c], w0)));
            float cs_own = reduce8_to_owner2(part2, m);
            float v_own = __fdividef(0.125f, cs_own + 1e-30f);
            #pragma unroll
            for (int c = 0; c < 4; c++) {
                vr2[c].x = __shfl_sync(FULLMASK, v_own, base + 2 * c);
                vr2[c].y = __shfl_sync(FULLMASK, v_own, base + 2 * c + 1);
            }
        }
    }

    // ---- Final fgw ----
    {
        float2 uu0 = make_float2(u0,u0), uu1 = make_float2(u1,u1), uu2 = make_float2(u2,u2);
        float2 Pa2[4], Pb2[4], Pc2[4];
        #pragma unroll
        for (int c = 0; c < 4; c++) {
            Pa2[c] = mul2(mul2(Ka2[c], vr2[c]), uu0);
            Pb2[c] = mul2(mul2(Kb2[c], vr2[c]), uu1);
            Pc2[c] = mul2(mul2(Kc2[c], vr2[c]), uu2);
        }
        float2 nA0[4], nAr[4];
        compute_nA2(Pa2, Pb2, Pc2, C2r, m, base, lane0, nA0, nAr);
        float2 acc = make_float2(0.f, 0.f);
        #pragma unroll
        for (int c = 0; c < 4; c++) {
            float2 nAa = lane0 ? nA0[c] : nAr[c];
            acc = fma2(add2(Mah[c], nAa), Pa2[c], acc);
            acc = fma2(add2(Mbh[c], nAr[c]), Pb2[c], acc);
            acc = fma2(add2(Mch[c], nAr[c]), Pc2[c], acc);
        }
        float loc = acc.x + acc.y;
        loc += __shfl_xor_sync(FULLMASK, loc, 1);
        loc += __shfl_xor_sync(FULLMASK, loc, 2);
        loc += __shfl_xor_sync(FULLMASK, loc, 4);
        if (lane0) fgw_s[t] = loc;
    }
    __syncthreads();

    if (tid < 8) {
        float o = __ldg(&bvec[tid]);
        #pragma unroll
        for (int tt = 0; tt < 16; tt++)
            o += fgw_s[tt] * __ldg(&Wm[tt * 8 + tid]);
        out[node * 8 + tid] = o;
    }
}

extern "C" void kernel_launch(void* const* d_in, const int* in_sizes, int n_in,
                              void* d_out, int out_size) {
    const float* x   = (const float*)d_in[0];
    const int*   ei  = (const int*)d_in[1];
    const float* lt  = (const float*)d_in[2];
    const float* tf  = (const float*)d_in[3];
    const float* Wm  = (const float*)d_in[4];
    const float* bv  = (const float*)d_in[5];
    float* out = (float*)d_out;

    const int N = in_sizes[0] / 128;
    const int* dst = ei + N * 16;

    precompute_kernel<<<(N + 7) / 8, 128>>>(x, lt, tf, N);
    otgnn_fgw_kernel<<<N, 128>>>(dst, Wm, bv, out);
}

// round 5
// speedup vs baseline: 4.0497x; 1.3340x over previous
#include <cuda_runtime.h>

#define FULLMASK 0xffffffffu
#define MAXN 16384

// Scratch (device globals — no allocation)
__device__ float g_G[MAXN * 128];   // G[j][tm] = x_j . tf_{t,m}
__device__ float g_xn2[MAXN];       // |x_j|^2
__device__ float g_tf2[128];        // |tf_{t,m}|^2
__device__ float g_C2s[128 * 8];    // symmetrized C2 rows

// ---------------- packed f32x2 helpers ----------------
union f2u { float2 f; unsigned long long u; };
__device__ __forceinline__ float2 fma2(float2 a, float2 b, float2 c) {
    f2u A, B, C, D; A.f = a; B.f = b; C.f = c;
    asm("fma.rn.f32x2 %0, %1, %2, %3;" : "=l"(D.u) : "l"(A.u), "l"(B.u), "l"(C.u));
    return D.f;
}
__device__ __forceinline__ float2 mul2(float2 a, float2 b) {
    f2u A, B, D; A.f = a; B.f = b;
    asm("mul.rn.f32x2 %0, %1, %2;" : "=l"(D.u) : "l"(A.u), "l"(B.u));
    return D.f;
}
__device__ __forceinline__ float2 add2(float2 a, float2 b) {
    f2u A, B, D; A.f = a; B.f = b;
    asm("add.rn.f32x2 %0, %1, %2;" : "=l"(D.u) : "l"(A.u), "l"(B.u));
    return D.f;
}
__device__ __forceinline__ float ex2(float x) {
    float r; asm("ex2.approx.f32 %0, %1;" : "=f"(r) : "f"(x)); return r;
}
__device__ __forceinline__ float2 bc2(float s) { return make_float2(s, s); }

// ---------------- Kernel A: precompute ----------------
__global__ void __launch_bounds__(128)
precompute_kernel(const float* __restrict__ x,
                  const float* __restrict__ lt,
                  const float* __restrict__ tf,
                  int N)
{
    __shared__ float xs[16][128];
    const int tid = threadIdx.x;
    const int n0  = blockIdx.x * 16;

    #pragma unroll
    for (int j = 0; j < 16; j++)
        xs[j][tid] = (n0 + j < N) ? __ldg(&x[(n0 + j) * 128 + tid]) : 0.f;
    __syncthreads();

    const float4* tfr = (const float4*)(tf + tid * 128);
    float acc[16];
    #pragma unroll
    for (int j = 0; j < 16; j++) acc[j] = 0.f;
    float tf2a = 0.f;
    #pragma unroll 2
    for (int c4 = 0; c4 < 32; c4++) {
        float4 tv = __ldg(&tfr[c4]);
        tf2a += tv.x*tv.x + tv.y*tv.y + tv.z*tv.z + tv.w*tv.w;
        #pragma unroll
        for (int j = 0; j < 16; j++) {
            float4 v = *(const float4*)&xs[j][c4 * 4];
            acc[j] += v.x*tv.x + v.y*tv.y + v.z*tv.z + v.w*tv.w;
        }
    }
    #pragma unroll
    for (int j = 0; j < 16; j++)
        if (n0 + j < N) g_G[(n0 + j) * 128 + tid] = acc[j];

    const int jn = tid >> 3, off = (tid & 7) * 16;
    float s = 0.f;
    #pragma unroll
    for (int k = 0; k < 16; k++) { float v = xs[jn][off + k]; s += v * v; }
    s += __shfl_xor_sync(FULLMASK, s, 1);
    s += __shfl_xor_sync(FULLMASK, s, 2);
    s += __shfl_xor_sync(FULLMASK, s, 4);
    if ((tid & 7) == 0 && n0 + jn < N) g_xn2[n0 + jn] = s;

    if (blockIdx.x == 0) {
        g_tf2[tid] = tf2a;
        const int t = tid >> 3, m = tid & 7;
        #pragma unroll
        for (int l = 0; l < 8; l++)
            g_C2s[tid * 8 + l] = 0.5f * (__ldg(&lt[(t * 8 + m) * 8 + l]) +
                                         __ldg(&lt[(t * 8 + l) * 8 + m]));
    }
}

// 4-lane reduce: lane l (within its 4-lane group) ends with float2 holding
// elements (2l, 2l+1) of the column sum over the group's 4 lanes.
__device__ __forceinline__ float2 reduce4_to_owner(const float2 q[4], int l) {
    bool h2 = (l & 2) != 0;
    float2 a0 = h2 ? q[2] : q[0], b0 = h2 ? q[0] : q[2];
    float2 a1 = h2 ? q[3] : q[1], b1 = h2 ? q[1] : q[3];
    b0.x = __shfl_xor_sync(FULLMASK, b0.x, 2);
    b0.y = __shfl_xor_sync(FULLMASK, b0.y, 2);
    b1.x = __shfl_xor_sync(FULLMASK, b1.x, 2);
    b1.y = __shfl_xor_sync(FULLMASK, b1.y, 2);
    a0 = add2(a0, b0); a1 = add2(a1, b1);
    bool h1 = (l & 1) != 0;
    float2 c = h1 ? a1 : a0, d = h1 ? a0 : a1;
    d.x = __shfl_xor_sync(FULLMASK, d.x, 1);
    d.y = __shfl_xor_sync(FULLMASK, d.y, 1);
    return add2(c, d);
}

// -EKC*A broadcast to all lanes: nA0s (rowset0, with row0 select) and nAr (rows>=1).
// K currently holds P. C2a/C2b are EKC-scaled rows 2l, 2l+1 of C2.
__device__ __forceinline__ void compute_nA(
    const float2 K[5][4], const float2 C2a[4], const float2 C2b[4],
    int l, int base4, bool l0,
    float2 nA0s[4], float2 nAr[4])
{
    float2 sp[4], w[4];
    #pragma unroll
    for (int c = 0; c < 4; c++) {
        float2 t0 = l0 ? bc2(0.f) : K[0][c];
        sp[c] = add2(add2(add2(t0, K[1][c]), add2(K[2][c], K[3][c])), K[4][c]);
    }
    float2 s_own = reduce4_to_owner(sp, l);
    s_own.x = -s_own.x; s_own.y = -s_own.y;
    #pragma unroll
    for (int c = 0; c < 4; c++)
        w[c] = fma2(bc2(s_own.y), C2b[c], mul2(bc2(s_own.x), C2a[c]));
    float2 nA0o = reduce4_to_owner(w, l);
    float2 nA0[4];
    #pragma unroll
    for (int k = 0; k < 4; k++) {
        nA0[k].x = __shfl_sync(FULLMASK, nA0o.x, base4 + k);
        nA0[k].y = __shfl_sync(FULLMASK, nA0o.y, base4 + k);
    }
    // P row 0 lives at lane base4's K[0][*]; lane l needs pair l
    float2 qk[4];
    #pragma unroll
    for (int k = 0; k < 4; k++) {
        qk[k].x = __shfl_sync(FULLMASK, K[0][k].x, base4);
        qk[k].y = __shfl_sync(FULLMASK, K[0][k].y, base4);
    }
    float2 pick = (l & 2) ? ((l & 1) ? qk[3] : qk[2]) : ((l & 1) ? qk[1] : qk[0]);
    pick.x = -pick.x; pick.y = -pick.y;
    #pragma unroll
    for (int c = 0; c < 4; c++)
        w[c] = fma2(bc2(pick.y), C2b[c], mul2(bc2(pick.x), C2a[c]));
    float2 nAro = reduce4_to_owner(w, l);
    #pragma unroll
    for (int k = 0; k < 4; k++) {
        nAr[k].x = __shfl_sync(FULLMASK, nAro.x, base4 + k);
        nAr[k].y = __shfl_sync(FULLMASK, nAro.y, base4 + k);
    }
    #pragma unroll
    for (int c = 0; c < 4; c++)
        nA0s[c] = l0 ? nA0[c] : nAr[c];
}

// ---------------- Kernel B: FGW, 4 lanes per (node,template) ----------------
__global__ void __launch_bounds__(64)
otgnn_fgw_kernel(const int* __restrict__ dst,
                 const float* __restrict__ Wm,
                 const float* __restrict__ bvec,
                 float* __restrict__ out)
{
    __shared__ int   idxs[17];
    __shared__ float xn2s[17];
    __shared__ float fgw_s[16];

    const int node = blockIdx.x;
    const int tid  = threadIdx.x;
    const int t    = tid >> 2;       // template 0..15
    const int l    = tid & 3;        // lane within 4-group
    const int lane = tid & 31;
    const int base4 = lane & 28;
    const bool l0 = (l == 0);

    if (tid < 17) {
        int id = tid ? __ldg(&dst[node * 16 + tid - 1]) : node;
        idxs[tid] = id;
        xn2s[tid] = g_xn2[id];
    }
    __syncthreads();

    const float EKC = 7.21347520444482f;  // 5 * log2(e)

    // C2 rows 2l, 2l+1 (unscaled first, for cc2)
    const float4* c2p = (const float4*)&g_C2s[(t * 8 + 2 * l) * 8];
    float4 ra0 = __ldg(&c2p[0]), ra1 = __ldg(&c2p[1]);
    float4 rb0 = __ldg(&c2p[2]), rb1 = __ldg(&c2p[3]);
    float2 C2a[4] = { {ra0.x,ra0.y},{ra0.z,ra0.w},{ra1.x,ra1.y},{ra1.z,ra1.w} };
    float2 C2b[4] = { {rb0.x,rb0.y},{rb0.z,rb0.w},{rb1.x,rb1.y},{rb1.z,rb1.w} };

    // cc2[c] = sum_l C2[l][c]^2 / 8, broadcast to all lanes
    float2 cc2f[4];
    {
        float2 qq[4];
        #pragma unroll
        for (int c = 0; c < 4; c++)
            qq[c] = add2(mul2(C2a[c], C2a[c]), mul2(C2b[c], C2b[c]));
        float2 ccf = reduce4_to_owner(qq, l);
        ccf.x *= 0.125f; ccf.y *= 0.125f;
        #pragma unroll
        for (int k = 0; k < 4; k++) {
            cc2f[k].x = __shfl_sync(FULLMASK, ccf.x, base4 + k);
            cc2f[k].y = __shfl_sync(FULLMASK, ccf.y, base4 + k);
        }
    }
    // scale C2 by EKC
    #pragma unroll
    for (int c = 0; c < 4; c++) {
        C2a[c] = mul2(C2a[c], bc2(EKC));
        C2b[c] = mul2(C2b[c], bc2(EKC));
    }

    // Mh[r][c] = (M + c1h + cc2) * 0.5 * EKC, 5 rowsets (rows 4r+l, r<4; row16)
    float2 Mh[5][4];
    {
        float2 tf2f[4];
        float4 ta = *(const float4*)&g_tf2[t * 8];
        float4 tb = *(const float4*)&g_tf2[t * 8 + 4];
        tf2f[0] = make_float2(ta.x, ta.y); tf2f[1] = make_float2(ta.z, ta.w);
        tf2f[2] = make_float2(tb.x, tb.y); tf2f[3] = make_float2(tb.z, tb.w);
        const float HF = 0.5f * EKC;
        #pragma unroll
        for (int r = 0; r < 5; r++) {
            int row = (r < 4) ? r * 4 + l : 16;
            int id = idxs[row];
            float n2 = xn2s[row];
            float4 g0 = __ldg((const float4*)&g_G[id * 128 + t * 8]);
            float4 g1 = __ldg((const float4*)&g_G[id * 128 + t * 8 + 4]);
            float gg[8] = {g0.x,g0.y,g0.z,g0.w,g1.x,g1.y,g1.z,g1.w};
            float c1h = (r == 0 && l0) ? (16.f / 17.f) : (1.f / 17.f);
            #pragma unroll
            for (int c = 0; c < 4; c++) {
                float mx = (n2 + tf2f[c].x - 2.f * gg[2*c])   * (1.f / 128.f);
                float my = (n2 + tf2f[c].y - 2.f * gg[2*c+1]) * (1.f / 128.f);
                Mh[r][c].x = (mx + c1h + cc2f[c].x) * HF;
                Mh[r][c].y = (my + c1h + cc2f[c].y) * HF;
            }
        }
    }

    // State: K rows (in f2 pairs), v, u
    float2 K[5][4], vr[4];
    float u[5];
    #pragma unroll
    for (int r = 0; r < 5; r++) {
        float init = (r == 4) ? (l0 ? 1.f / 136.f : 0.f) : (1.f / 136.f);
        #pragma unroll
        for (int c = 0; c < 4; c++) K[r][c] = bc2(init);
        u[r] = 1.f;
    }
    #pragma unroll
    for (int c = 0; c < 4; c++) vr[c] = bc2(1.f);

    #pragma unroll 1
    for (int outer = 0; outer < 5; outer++) {
        // P in place: K <- u * K * v
        #pragma unroll
        for (int r = 0; r < 5; r++) {
            float2 uf = bc2(u[r]);
            #pragma unroll
            for (int c = 0; c < 4; c++) K[r][c] = mul2(mul2(K[r][c], vr[c]), uf);
        }
        float2 nA0s[4], nAr[4];
        compute_nA(K, C2a, C2b, l, base4, l0, nA0s, nAr);

        // gmin over the tile (EKC-scaled domain)
        float gm = 3.4e38f;
        #pragma unroll
        for (int c = 0; c < 4; c++) {
            float2 G0 = add2(Mh[0][c], nA0s[c]);
            gm = fminf(gm, fminf(G0.x, G0.y));
            #pragma unroll
            for (int r = 1; r < 5; r++) {
                float2 G = add2(Mh[r][c], nAr[c]);
                gm = fminf(gm, fminf(G.x, G.y));
            }
        }
        gm = fminf(gm, __shfl_xor_sync(FULLMASK, gm, 1));
        gm = fminf(gm, __shfl_xor_sync(FULLMASK, gm, 2));

        // K <- P * ex2(gm - G)
        float2 gm2 = bc2(gm), n1 = bc2(-1.f);
        #pragma unroll
        for (int c = 0; c < 4; c++) {
            float2 G = add2(Mh[0][c], nA0s[c]);
            float2 e = fma2(G, n1, gm2); e.x = ex2(e.x); e.y = ex2(e.y);
            K[0][c] = mul2(K[0][c], e);
            #pragma unroll
            for (int r = 1; r < 5; r++) {
                G = add2(Mh[r][c], nAr[c]);
                e = fma2(G, n1, gm2); e.x = ex2(e.x); e.y = ex2(e.y);
                K[r][c] = mul2(K[r][c], e);
            }
            vr[c] = bc2(1.f);
        }

        // Sinkhorn
        #pragma unroll 1
        for (int inner = 0; inner < 10; inner++) {
            #pragma unroll
            for (int r = 0; r < 5; r++) {
                float2 d = mul2(K[r][0], vr[0]);
                d = fma2(K[r][1], vr[1], d);
                d = fma2(K[r][2], vr[2], d);
                d = fma2(K[r][3], vr[3], d);
                u[r] = __fdividef(1.f / 17.f, d.x + d.y + 1e-30f);
            }
            float2 part[4];
            #pragma unroll
            for (int c = 0; c < 4; c++) {
                part[c] = mul2(K[0][c], bc2(u[0]));
                #pragma unroll
                for (int r = 1; r < 5; r++)
                    part[c] = fma2(K[r][c], bc2(u[r]), part[c]);
            }
            float2 cs = reduce4_to_owner(part, l);
            float2 vo;
            vo.x = __fdividef(0.125f, cs.x + 1e-30f);
            vo.y = __fdividef(0.125f, cs.y + 1e-30f);
            #pragma unroll
            for (int k = 0; k < 4; k++) {
                vr[k].x = __shfl_sync(FULLMASK, vo.x, base4 + k);
                vr[k].y = __shfl_sync(FULLMASK, vo.y, base4 + k);
            }
        }
    }

    // ---- Final: P in place, fgw = sum(G .* P) / EKC ----
    #pragma unroll
    for (int r = 0; r < 5; r++) {
        float2 uf = bc2(u[r]);
        #pragma unroll
        for (int c = 0; c < 4; c++) K[r][c] = mul2(mul2(K[r][c], vr[c]), uf);
    }
    {
        float2 nA0s[4], nAr[4];
        compute_nA(K, C2a, C2b, l, base4, l0, nA0s, nAr);
        float2 accv = bc2(0.f);
        #pragma unroll
        for (int c = 0; c < 4; c++) {
            accv = fma2(add2(Mh[0][c], nA0s[c]), K[0][c], accv);
            #pragma unroll
            for (int r = 1; r < 5; r++)
                accv = fma2(add2(Mh[r][c], nAr[c]), K[r][c], accv);
        }
        float loc = accv.x + accv.y;
        loc += __shfl_xor_sync(FULLMASK, loc, 1);
        loc += __shfl_xor_sync(FULLMASK, loc, 2);
        if (l0) fgw_s[t] = loc * (1.f / EKC);
    }
    __syncthreads();

    if (tid < 8) {
        float o = __ldg(&bvec[tid]);
        #pragma unroll
        for (int tt = 0; tt < 16; tt++)
            o += fgw_s[tt] * __ldg(&Wm[tt * 8 + tid]);
        out[node * 8 + tid] = o;
    }
}

extern "C" void kernel_launch(void* const* d_in, const int* in_sizes, int n_in,
                              void* d_out, int out_size) {
    const float* x   = (const float*)d_in[0];
    const int*   ei  = (const int*)d_in[1];
    const float* lt  = (const float*)d_in[2];
    const float* tf  = (const float*)d_in[3];
    const float* Wm  = (const float*)d_in[4];
    const float* bv  = (const float*)d_in[5];
    float* out = (float*)d_out;

    const int N = in_sizes[0] / 128;
    const int* dst = ei + N * 16;

    precompute_kernel<<<(N + 15) / 16, 128>>>(x, lt, tf, N);
    otgnn_fgw_kernel<<<N, 64>>>(dst, Wm, bv, out);
}

// round 6
// speedup vs baseline: 4.1677x; 1.0291x over previous
#include <cuda_runtime.h>

#define FULLMASK 0xffffffffu
#define MAXN 16384

// Scratch (device globals — no allocation)
__device__ float g_G[MAXN * 128];   // G[j][tm] = x_j . tf_{t,m}
__device__ float g_xn2[MAXN];       // |x_j|^2
__device__ float g_tf2[128];        // |tf_{t,m}|^2
__device__ float g_C2s[128 * 8];    // symmetrized C2 rows

// ---------------- packed f32x2 helpers ----------------
union f2u { float2 f; unsigned long long u; };
__device__ __forceinline__ float2 fma2(float2 a, float2 b, float2 c) {
    f2u A, B, C, D; A.f = a; B.f = b; C.f = c;
    asm("fma.rn.f32x2 %0, %1, %2, %3;" : "=l"(D.u) : "l"(A.u), "l"(B.u), "l"(C.u));
    return D.f;
}
__device__ __forceinline__ float2 mul2(float2 a, float2 b) {
    f2u A, B, D; A.f = a; B.f = b;
    asm("mul.rn.f32x2 %0, %1, %2;" : "=l"(D.u) : "l"(A.u), "l"(B.u));
    return D.f;
}
__device__ __forceinline__ float2 add2(float2 a, float2 b) {
    f2u A, B, D; A.f = a; B.f = b;
    asm("add.rn.f32x2 %0, %1, %2;" : "=l"(D.u) : "l"(A.u), "l"(B.u));
    return D.f;
}
__device__ __forceinline__ float ex2(float x) {
    float r; asm("ex2.approx.f32 %0, %1;" : "=f"(r) : "f"(x)); return r;
}
__device__ __forceinline__ float2 bc2(float s) { return make_float2(s, s); }

// ---------------- Kernel A: precompute (32 nodes/block) ----------------
__global__ void __launch_bounds__(128)
precompute_kernel(const float* __restrict__ x,
                  const float* __restrict__ lt,
                  const float* __restrict__ tf,
                  int N)
{
    __shared__ float xs[32][128];
    const int tid = threadIdx.x;
    const int n0  = blockIdx.x * 32;

    #pragma unroll
    for (int j = 0; j < 32; j++)
        xs[j][tid] = (n0 + j < N) ? __ldg(&x[(n0 + j) * 128 + tid]) : 0.f;
    __syncthreads();

    const float4* tfr = (const float4*)(tf + tid * 128);
    float acc[32];
    #pragma unroll
    for (int j = 0; j < 32; j++) acc[j] = 0.f;
    float tf2a = 0.f;
    #pragma unroll 1
    for (int c4 = 0; c4 < 32; c4++) {
        float4 tv = __ldg(&tfr[c4]);
        tf2a += tv.x*tv.x + tv.y*tv.y + tv.z*tv.z + tv.w*tv.w;
        #pragma unroll
        for (int j = 0; j < 32; j++) {
            float4 v = *(const float4*)&xs[j][c4 * 4];
            acc[j] += v.x*tv.x + v.y*tv.y + v.z*tv.z + v.w*tv.w;
        }
    }
    #pragma unroll
    for (int j = 0; j < 32; j++)
        if (n0 + j < N) g_G[(n0 + j) * 128 + tid] = acc[j];

    // xn2: 4 threads per node, 32 elements each
    const int jn = tid >> 2, off = (tid & 3) * 32;
    float s = 0.f;
    #pragma unroll
    for (int k = 0; k < 32; k++) { float v = xs[jn][off + k]; s += v * v; }
    s += __shfl_xor_sync(FULLMASK, s, 1);
    s += __shfl_xor_sync(FULLMASK, s, 2);
    if ((tid & 3) == 0 && n0 + jn < N) g_xn2[n0 + jn] = s;

    if (blockIdx.x == 0) {
        g_tf2[tid] = tf2a;
        const int t = tid >> 3, m = tid & 7;
        #pragma unroll
        for (int l = 0; l < 8; l++)
            g_C2s[tid * 8 + l] = 0.5f * (__ldg(&lt[(t * 8 + m) * 8 + l]) +
                                         __ldg(&lt[(t * 8 + l) * 8 + m]));
    }
}

// 4-lane reduce: lane l ends with float2 of elements (2l, 2l+1) of the
// column sum over the group's 4 lanes.
__device__ __forceinline__ float2 reduce4_to_owner(const float2 q[4], int l) {
    bool h2 = (l & 2) != 0;
    float2 a0 = h2 ? q[2] : q[0], b0 = h2 ? q[0] : q[2];
    float2 a1 = h2 ? q[3] : q[1], b1 = h2 ? q[1] : q[3];
    b0.x = __shfl_xor_sync(FULLMASK, b0.x, 2);
    b0.y = __shfl_xor_sync(FULLMASK, b0.y, 2);
    b1.x = __shfl_xor_sync(FULLMASK, b1.x, 2);
    b1.y = __shfl_xor_sync(FULLMASK, b1.y, 2);
    a0 = add2(a0, b0); a1 = add2(a1, b1);
    bool h1 = (l & 1) != 0;
    float2 c = h1 ? a1 : a0, d = h1 ? a0 : a1;
    d.x = __shfl_xor_sync(FULLMASK, d.x, 1);
    d.y = __shfl_xor_sync(FULLMASK, d.y, 1);
    return add2(c, d);
}

// -EKC*A broadcast: nA0s (rowset0 incl. row-0 select), nAr (rows>=1).
// K currently holds P. C2a/C2b are EKC-scaled rows 2l, 2l+1 of C2.
__device__ __forceinline__ void compute_nA(
    const float2 K[5][4], const float2 C2a[4], const float2 C2b[4],
    int l, int base4, bool l0,
    float2 nA0s[4], float2 nAr[4])
{
    float2 sp[4], w[4];
    #pragma unroll
    for (int c = 0; c < 4; c++) {
        float2 t0 = l0 ? bc2(0.f) : K[0][c];
        sp[c] = add2(add2(add2(t0, K[1][c]), add2(K[2][c], K[3][c])), K[4][c]);
    }
    float2 s_own = reduce4_to_owner(sp, l);
    s_own.x = -s_own.x; s_own.y = -s_own.y;
    #pragma unroll
    for (int c = 0; c < 4; c++)
        w[c] = fma2(bc2(s_own.y), C2b[c], mul2(bc2(s_own.x), C2a[c]));
    float2 nA0o = reduce4_to_owner(w, l);
    float2 nA0[4];
    #pragma unroll
    for (int k = 0; k < 4; k++) {
        nA0[k].x = __shfl_sync(FULLMASK, nA0o.x, base4 + k);
        nA0[k].y = __shfl_sync(FULLMASK, nA0o.y, base4 + k);
    }
    float2 qk[4];
    #pragma unroll
    for (int k = 0; k < 4; k++) {
        qk[k].x = __shfl_sync(FULLMASK, K[0][k].x, base4);
        qk[k].y = __shfl_sync(FULLMASK, K[0][k].y, base4);
    }
    float2 pick = (l & 2) ? ((l & 1) ? qk[3] : qk[2]) : ((l & 1) ? qk[1] : qk[0]);
    pick.x = -pick.x; pick.y = -pick.y;
    #pragma unroll
    for (int c = 0; c < 4; c++)
        w[c] = fma2(bc2(pick.y), C2b[c], mul2(bc2(pick.x), C2a[c]));
    float2 nAro = reduce4_to_owner(w, l);
    #pragma unroll
    for (int k = 0; k < 4; k++) {
        nAr[k].x = __shfl_sync(FULLMASK, nAro.x, base4 + k);
        nAr[k].y = __shfl_sync(FULLMASK, nAro.y, base4 + k);
    }
    #pragma unroll
    for (int c = 0; c < 4; c++)
        nA0s[c] = l0 ? nA0[c] : nAr[c];
}

// ---------------- Kernel B: FGW, 4 lanes per (node,template) ----------------
__global__ void __launch_bounds__(64, 9)
otgnn_fgw_kernel(const int* __restrict__ dst,
                 const float* __restrict__ Wm,
                 const float* __restrict__ bvec,
                 float* __restrict__ out)
{
    __shared__ float2 Mh_s[20][64];   // [r*4+c][tid], conflict-free
    __shared__ int   idxs[17];
    __shared__ float xn2s[17];
    __shared__ float fgw_s[16];

    const int node = blockIdx.x;
    const int tid  = threadIdx.x;
    const int t    = tid >> 2;
    const int l    = tid & 3;
    const int lane = tid & 31;
    const int base4 = lane & 28;
    const bool l0 = (l == 0);

    if (tid < 17) {
        int id = tid ? __ldg(&dst[node * 16 + tid - 1]) : node;
        idxs[tid] = id;
        xn2s[tid] = g_xn2[id];
    }
    __syncthreads();

    const float EKC = 7.21347520444482f;  // 5 * log2(e)

    // C2 rows 2l, 2l+1 (unscaled first)
    const float4* c2p = (const float4*)&g_C2s[(t * 8 + 2 * l) * 8];
    float4 ra0 = __ldg(&c2p[0]), ra1 = __ldg(&c2p[1]);
    float4 rb0 = __ldg(&c2p[2]), rb1 = __ldg(&c2p[3]);
    float2 C2a[4] = { {ra0.x,ra0.y},{ra0.z,ra0.w},{ra1.x,ra1.y},{ra1.z,ra1.w} };
    float2 C2b[4] = { {rb0.x,rb0.y},{rb0.z,rb0.w},{rb1.x,rb1.y},{rb1.z,rb1.w} };

    // cc2[c] = sum_l C2[l][c]^2 / 8, broadcast
    float2 cc2f[4];
    {
        float2 qq[4];
        #pragma unroll
        for (int c = 0; c < 4; c++)
            qq[c] = add2(mul2(C2a[c], C2a[c]), mul2(C2b[c], C2b[c]));
        float2 ccf = reduce4_to_owner(qq, l);
        ccf.x *= 0.125f; ccf.y *= 0.125f;
        #pragma unroll
        for (int k = 0; k < 4; k++) {
            cc2f[k].x = __shfl_sync(FULLMASK, ccf.x, base4 + k);
            cc2f[k].y = __shfl_sync(FULLMASK, ccf.y, base4 + k);
        }
    }
    #pragma unroll
    for (int c = 0; c < 4; c++) {
        C2a[c] = mul2(C2a[c], bc2(EKC));
        C2b[c] = mul2(C2b[c], bc2(EKC));
    }

    // Mh (EKC-scaled) into smem: rowsets r<4 -> row 4r+l, r=4 -> row 16
    {
        float2 tf2f[4];
        float4 ta = *(const float4*)&g_tf2[t * 8];
        float4 tb = *(const float4*)&g_tf2[t * 8 + 4];
        tf2f[0] = make_float2(ta.x, ta.y); tf2f[1] = make_float2(ta.z, ta.w);
        tf2f[2] = make_float2(tb.x, tb.y); tf2f[3] = make_float2(tb.z, tb.w);
        const float HF = 0.5f * EKC;
        #pragma unroll
        for (int r = 0; r < 5; r++) {
            int row = (r < 4) ? r * 4 + l : 16;
            int id = idxs[row];
            float n2 = xn2s[row];
            float4 g0 = __ldg((const float4*)&g_G[id * 128 + t * 8]);
            float4 g1 = __ldg((const float4*)&g_G[id * 128 + t * 8 + 4]);
            float gg[8] = {g0.x,g0.y,g0.z,g0.w,g1.x,g1.y,g1.z,g1.w};
            float c1h = (r == 0 && l0) ? (16.f / 17.f) : (1.f / 17.f);
            #pragma unroll
            for (int c = 0; c < 4; c++) {
                float mx = (n2 + tf2f[c].x - 2.f * gg[2*c])   * (1.f / 128.f);
                float my = (n2 + tf2f[c].y - 2.f * gg[2*c+1]) * (1.f / 128.f);
                Mh_s[r * 4 + c][tid] = make_float2((mx + c1h + cc2f[c].x) * HF,
                                                   (my + c1h + cc2f[c].y) * HF);
            }
        }
    }

    // State
    float2 K[5][4], vr[4];
    float u[5];
    #pragma unroll
    for (int r = 0; r < 5; r++) {
        float init = (r == 4) ? (l0 ? 1.f / 136.f : 0.f) : (1.f / 136.f);
        #pragma unroll
        for (int c = 0; c < 4; c++) K[r][c] = bc2(init);
        u[r] = 1.f;
    }
    #pragma unroll
    for (int c = 0; c < 4; c++) vr[c] = bc2(1.f);

    #pragma unroll 1
    for (int outer = 0; outer < 5; outer++) {
        // P in place
        #pragma unroll
        for (int r = 0; r < 5; r++) {
            float2 uf = bc2(u[r]);
            #pragma unroll
            for (int c = 0; c < 4; c++) K[r][c] = mul2(mul2(K[r][c], vr[c]), uf);
        }
        float2 nA0s[4], nAr[4];
        compute_nA(K, C2a, C2b, l, base4, l0, nA0s, nAr);

        // gmin (reads Mh from smem)
        float gm = 3.4e38f;
        #pragma unroll
        for (int c = 0; c < 4; c++) {
            float2 G0 = add2(Mh_s[c][tid], nA0s[c]);
            gm = fminf(gm, fminf(G0.x, G0.y));
            #pragma unroll
            for (int r = 1; r < 5; r++) {
                float2 G = add2(Mh_s[r * 4 + c][tid], nAr[c]);
                gm = fminf(gm, fminf(G.x, G.y));
            }
        }
        gm = fminf(gm, __shfl_xor_sync(FULLMASK, gm, 1));
        gm = fminf(gm, __shfl_xor_sync(FULLMASK, gm, 2));

        // K <- P * ex2(gm - G) (recompute G from smem)
        float2 gm2 = bc2(gm), n1 = bc2(-1.f);
        #pragma unroll
        for (int c = 0; c < 4; c++) {
            float2 G = add2(Mh_s[c][tid], nA0s[c]);
            float2 e = fma2(G, n1, gm2); e.x = ex2(e.x); e.y = ex2(e.y);
            K[0][c] = mul2(K[0][c], e);
            #pragma unroll
            for (int r = 1; r < 5; r++) {
                G = add2(Mh_s[r * 4 + c][tid], nAr[c]);
                e = fma2(G, n1, gm2); e.x = ex2(e.x); e.y = ex2(e.y);
                K[r][c] = mul2(K[r][c], e);
            }
            vr[c] = bc2(1.f);
        }

        // Sinkhorn
        #pragma unroll 1
        for (int inner = 0; inner < 10; inner++) {
            #pragma unroll
            for (int r = 0; r < 5; r++) {
                float2 d = mul2(K[r][0], vr[0]);
                d = fma2(K[r][1], vr[1], d);
                d = fma2(K[r][2], vr[2], d);
                d = fma2(K[r][3], vr[3], d);
                u[r] = __fdividef(1.f / 17.f, d.x + d.y + 1e-30f);
            }
            float2 part[4];
            #pragma unroll
            for (int c = 0; c < 4; c++) {
                part[c] = mul2(K[0][c], bc2(u[0]));
                #pragma unroll
                for (int r = 1; r < 5; r++)
                    part[c] = fma2(K[r][c], bc2(u[r]), part[c]);
            }
            float2 cs = reduce4_to_owner(part, l);
            float2 vo;
            vo.x = __fdividef(0.125f, cs.x + 1e-30f);
            vo.y = __fdividef(0.125f, cs.y + 1e-30f);
            #pragma unroll
            for (int k = 0; k < 4; k++) {
                vr[k].x = __shfl_sync(FULLMASK, vo.x, base4 + k);
                vr[k].y = __shfl_sync(FULLMASK, vo.y, base4 + k);
            }
        }
    }

    // ---- Final: P in place, fgw = sum(G .* P) / EKC ----
    #pragma unroll
    for (int r = 0; r < 5; r++) {
        float2 uf = bc2(u[r]);
        #pragma unroll
        for (int c = 0; c < 4; c++) K[r][c] = mul2(mul2(K[r][c], vr[c]), uf);
    }
    {
        float2 nA0s[4], nAr[4];
        compute_nA(K, C2a, C2b, l, base4, l0, nA0s, nAr);
        float2 accv = bc2(0.f);
        #pragma unroll
        for (int c = 0; c < 4; c++) {
            accv = fma2(add2(Mh_s[c][tid], nA0s[c]), K[0][c], accv);
            #pragma unroll
            for (int r = 1; r < 5; r++)
                accv = fma2(add2(Mh_s[r * 4 + c][tid], nAr[c]), K[r][c], accv);
        }
        float loc = accv.x + accv.y;
        loc += __shfl_xor_sync(FULLMASK, loc, 1);
        loc += __shfl_xor_sync(FULLMASK, loc, 2);
        if (l0) fgw_s[t] = loc * (1.f / EKC);
    }
    __syncthreads();

    if (tid < 8) {
        float o = __ldg(&bvec[tid]);
        #pragma unroll
        for (int tt = 0; tt < 16; tt++)
            o += fgw_s[tt] * __ldg(&Wm[tt * 8 + tid]);
        out[node * 8 + tid] = o;
    }
}

extern "C" void kernel_launch(void* const* d_in, const int* in_sizes, int n_in,
                              void* d_out, int out_size) {
    const float* x   = (const float*)d_in[0];
    const int*   ei  = (const int*)d_in[1];
    const float* lt  = (const float*)d_in[2];
    const float* tf  = (const float*)d_in[3];
    const float* Wm  = (const float*)d_in[4];
    const float* bv  = (const float*)d_in[5];
    float* out = (float*)d_out;

    const int N = in_sizes[0] / 128;
    const int* dst = ei + N * 16;

    precompute_kernel<<<(N + 31) / 32, 128>>>(x, lt, tf, N);
    otgnn_fgw_kernel<<<N, 64>>>(dst, Wm, bv, out);
}

// round 7
// speedup vs baseline: 4.4856x; 1.0763x over previous
#include <cuda_runtime.h>

#define FULLMASK 0xffffffffu
#define MAXN 16384

// Scratch (device globals — no allocation)
__device__ float g_G[MAXN * 128];   // G[j][tm] = x_j . tf_{t,m}
__device__ float g_xn2[MAXN];       // |x_j|^2
__device__ float g_tf2[128];        // |tf_{t,m}|^2
__device__ float g_C2s[128 * 8];    // symmetrized C2 rows

// ---------------- packed f32x2 helpers ----------------
union f2u { float2 f; unsigned long long u; };
__device__ __forceinline__ float2 fma2(float2 a, float2 b, float2 c) {
    f2u A, B, C, D; A.f = a; B.f = b; C.f = c;
    asm("fma.rn.f32x2 %0, %1, %2, %3;" : "=l"(D.u) : "l"(A.u), "l"(B.u), "l"(C.u));
    return D.f;
}
__device__ __forceinline__ float2 mul2(float2 a, float2 b) {
    f2u A, B, D; A.f = a; B.f = b;
    asm("mul.rn.f32x2 %0, %1, %2;" : "=l"(D.u) : "l"(A.u), "l"(B.u));
    return D.f;
}
__device__ __forceinline__ float2 add2(float2 a, float2 b) {
    f2u A, B, D; A.f = a; B.f = b;
    asm("add.rn.f32x2 %0, %1, %2;" : "=l"(D.u) : "l"(A.u), "l"(B.u));
    return D.f;
}
__device__ __forceinline__ float ex2(float x) {
    float r; asm("ex2.approx.f32 %0, %1;" : "=f"(r) : "f"(x)); return r;
}
__device__ __forceinline__ float2 bc2(float s) { return make_float2(s, s); }

// ---------------- Kernel A: precompute (32 nodes/block) ----------------
__global__ void __launch_bounds__(128)
precompute_kernel(const float* __restrict__ x,
                  const float* __restrict__ lt,
                  const float* __restrict__ tf,
                  int N)
{
    __shared__ float xs[32][128];
    const int tid = threadIdx.x;
    const int n0  = blockIdx.x * 32;

    #pragma unroll
    for (int j = 0; j < 32; j++)
        xs[j][tid] = (n0 + j < N) ? __ldg(&x[(n0 + j) * 128 + tid]) : 0.f;
    __syncthreads();

    const float4* tfr = (const float4*)(tf + tid * 128);
    float acc[32];
    #pragma unroll
    for (int j = 0; j < 32; j++) acc[j] = 0.f;
    float tf2a = 0.f;
    #pragma unroll 1
    for (int c4 = 0; c4 < 32; c4++) {
        float4 tv = __ldg(&tfr[c4]);
        tf2a += tv.x*tv.x + tv.y*tv.y + tv.z*tv.z + tv.w*tv.w;
        #pragma unroll
        for (int j = 0; j < 32; j++) {
            float4 v = *(const float4*)&xs[j][c4 * 4];
            acc[j] += v.x*tv.x + v.y*tv.y + v.z*tv.z + v.w*tv.w;
        }
    }
    #pragma unroll
    for (int j = 0; j < 32; j++)
        if (n0 + j < N) g_G[(n0 + j) * 128 + tid] = acc[j];

    const int jn = tid >> 2, off = (tid & 3) * 32;
    float s = 0.f;
    #pragma unroll
    for (int k = 0; k < 32; k++) { float v = xs[jn][off + k]; s += v * v; }
    s += __shfl_xor_sync(FULLMASK, s, 1);
    s += __shfl_xor_sync(FULLMASK, s, 2);
    if ((tid & 3) == 0 && n0 + jn < N) g_xn2[n0 + jn] = s;

    if (blockIdx.x == 0) {
        g_tf2[tid] = tf2a;
        const int t = tid >> 3, m = tid & 7;
        #pragma unroll
        for (int l = 0; l < 8; l++)
            g_C2s[tid * 8 + l] = 0.5f * (__ldg(&lt[(t * 8 + m) * 8 + l]) +
                                         __ldg(&lt[(t * 8 + l) * 8 + m]));
    }
}

// +EKC*A for the star graph, 2-lane groups. K holds P.
// C2h = EKC-scaled C2 rows 4l..4l+3 (lane's own columns, by symmetry).
// Outputs full 8-wide vectors pA0f (row 0 of A) and pArf (rows >= 1).
__device__ __forceinline__ void compute_pA(
    const float2 K[9][4], const float2 C2h[4][4],
    int l, int mate_src,
    float2 pA0f[4], float2 pArf[4])
{
    // s[c] = sum over rows >= 1 of P[row][c]
    float2 s2[4];
    #pragma unroll
    for (int c = 0; c < 4; c++) {
        float2 a = (l == 0) ? bc2(0.f) : K[0][c];
        #pragma unroll
        for (int r = 1; r < 9; r++) a = add2(a, K[r][c]);
        a.x += __shfl_xor_sync(FULLMASK, a.x, 1);
        a.y += __shfl_xor_sync(FULLMASK, a.y, 1);
        s2[c] = a;
    }
    // p0 = P row 0 (held by even lane's K[0])
    float2 p02[4];
    #pragma unroll
    for (int c = 0; c < 4; c++) {
        p02[c].x = __shfl_sync(FULLMASK, K[0][c].x, mate_src);
        p02[c].y = __shfl_sync(FULLMASK, K[0][c].y, mate_src);
    }
    // matvec for own 4 columns: A[col 4l+j] = dot(vec, C2 row 4l+j)
    float osA[4], osP[4];
    #pragma unroll
    for (int j = 0; j < 4; j++) {
        float2 aA = mul2(s2[0], C2h[j][0]);
        float2 aP = mul2(p02[0], C2h[j][0]);
        #pragma unroll
        for (int c = 1; c < 4; c++) {
            aA = fma2(s2[c],  C2h[j][c], aA);
            aP = fma2(p02[c], C2h[j][c], aP);
        }
        osA[j] = aA.x + aA.y;
        osP[j] = aP.x + aP.y;
    }
    float2 oA0 = make_float2(osA[0], osA[1]), oA1 = make_float2(osA[2], osA[3]);
    float2 oP0 = make_float2(osP[0], osP[1]), oP1 = make_float2(osP[2], osP[3]);
    float2 mA0, mA1, mP0, mP1;
    mA0.x = __shfl_xor_sync(FULLMASK, oA0.x, 1); mA0.y = __shfl_xor_sync(FULLMASK, oA0.y, 1);
    mA1.x = __shfl_xor_sync(FULLMASK, oA1.x, 1); mA1.y = __shfl_xor_sync(FULLMASK, oA1.y, 1);
    mP0.x = __shfl_xor_sync(FULLMASK, oP0.x, 1); mP0.y = __shfl_xor_sync(FULLMASK, oP0.y, 1);
    mP1.x = __shfl_xor_sync(FULLMASK, oP1.x, 1); mP1.y = __shfl_xor_sync(FULLMASK, oP1.y, 1);
    bool li = (l != 0);
    pA0f[0] = li ? mA0 : oA0; pA0f[1] = li ? mA1 : oA1;
    pA0f[2] = li ? oA0 : mA0; pA0f[3] = li ? oA1 : mA1;
    pArf[0] = li ? mP0 : oP0; pArf[1] = li ? mP1 : oP1;
    pArf[2] = li ? oP0 : mP0; pArf[3] = li ? oP1 : mP1;
}

// ---------------- Kernel B: FGW, 2 lanes per (node,template) ----------------
__global__ void __launch_bounds__(64, 6)
otgnn_fgw_kernel(const int* __restrict__ dst,
                 const float* __restrict__ Wm,
                 const float* __restrict__ bvec,
                 float* __restrict__ out)
{
    __shared__ float2 Mh_s[36][64];   // thread-private slots, conflict-free
    __shared__ int   idxs[2][17];
    __shared__ float xn2s[2][17];
    __shared__ float fgw_s[2][16];

    const int tid  = threadIdx.x;
    const int w    = tid >> 5;                 // warp -> node
    const int lane = tid & 31;
    const int node = blockIdx.x * 2 + w;
    const int t    = lane >> 1;                // template 0..15
    const int l    = lane & 1;
    const int mate_src = lane & ~1;
    const bool l0 = (l == 0);

    if (lane < 17) {
        int id = lane ? __ldg(&dst[node * 16 + lane - 1]) : node;
        idxs[w][lane] = id;
        xn2s[w][lane] = g_xn2[id];
    }
    __syncwarp();

    const float EKC = 7.21347520444482f;  // 5 * log2(e)

    // Own C2 rows 4l..4l+3 (unscaled first, for cc2)
    float2 C2h[4][4];
    #pragma unroll
    for (int j = 0; j < 4; j++) {
        const float4* p = (const float4*)&g_C2s[(t * 8 + 4 * l + j) * 8];
        float4 a = __ldg(&p[0]), b = __ldg(&p[1]);
        C2h[j][0] = make_float2(a.x, a.y); C2h[j][1] = make_float2(a.z, a.w);
        C2h[j][2] = make_float2(b.x, b.y); C2h[j][3] = make_float2(b.z, b.w);
    }
    // cc2[c] = (1/8) sum_rows C2[row][c]^2 (allreduce partial over own rows)
    float2 cc2f[4];
    #pragma unroll
    for (int c = 0; c < 4; c++) {
        float2 a = mul2(C2h[0][c], C2h[0][c]);
        a = fma2(C2h[1][c], C2h[1][c], a);
        a = fma2(C2h[2][c], C2h[2][c], a);
        a = fma2(C2h[3][c], C2h[3][c], a);
        a.x += __shfl_xor_sync(FULLMASK, a.x, 1);
        a.y += __shfl_xor_sync(FULLMASK, a.y, 1);
        cc2f[c] = make_float2(a.x * 0.125f, a.y * 0.125f);
    }
    // scale C2 by EKC
    #pragma unroll
    for (int j = 0; j < 4; j++)
        #pragma unroll
        for (int c = 0; c < 4; c++) C2h[j][c] = mul2(C2h[j][c], bc2(EKC));

    // Mhn = -(M + c1h + cc2) * 0.5 * EKC  into thread-private smem
    {
        float2 tf2f[4];
        float4 ta = *(const float4*)&g_tf2[t * 8];
        float4 tb = *(const float4*)&g_tf2[t * 8 + 4];
        tf2f[0] = make_float2(ta.x, ta.y); tf2f[1] = make_float2(ta.z, ta.w);
        tf2f[2] = make_float2(tb.x, tb.y); tf2f[3] = make_float2(tb.z, tb.w);
        const float HF = -0.5f * EKC;
        #pragma unroll
        for (int r = 0; r < 9; r++) {
            bool have = (r < 8) || l0;
            if (have) {
                int row = (r < 8) ? 2 * r + l : 16;
                int id = idxs[w][row];
                float n2 = xn2s[w][row];
                float4 g0 = __ldg((const float4*)&g_G[id * 128 + t * 8]);
                float4 g1 = __ldg((const float4*)&g_G[id * 128 + t * 8 + 4]);
                float gg[8] = {g0.x,g0.y,g0.z,g0.w,g1.x,g1.y,g1.z,g1.w};
                float c1h = (r == 0 && l0) ? (16.f / 17.f) : (1.f / 17.f);
                #pragma unroll
                for (int c = 0; c < 4; c++) {
                    float mx = (n2 + tf2f[c].x - 2.f * gg[2*c])   * (1.f / 128.f);
                    float my = (n2 + tf2f[c].y - 2.f * gg[2*c+1]) * (1.f / 128.f);
                    Mh_s[r * 4 + c][tid] = make_float2((mx + c1h + cc2f[c].x) * HF,
                                                       (my + c1h + cc2f[c].y) * HF);
                }
            } else {
                #pragma unroll
                for (int c = 0; c < 4; c++) Mh_s[r * 4 + c][tid] = bc2(0.f);
            }
        }
    }

    // State: K rowsets (rows 2r+l for r<8; row 16 on lane0), v, u
    float2 K[9][4], vr[4];
    float u[9];
    #pragma unroll
    for (int r = 0; r < 9; r++) {
        float init = (r == 8) ? (l0 ? 1.f / 136.f : 0.f) : (1.f / 136.f);
        #pragma unroll
        for (int c = 0; c < 4; c++) K[r][c] = bc2(init);
        u[r] = 1.f;
    }
    #pragma unroll
    for (int c = 0; c < 4; c++) vr[c] = bc2(1.f);

    #pragma unroll 1
    for (int outer = 0; outer < 5; outer++) {
        // P in place: K <- u * K * v
        #pragma unroll
        for (int r = 0; r < 9; r++) {
            float2 uf = bc2(u[r]);
            #pragma unroll
            for (int c = 0; c < 4; c++) K[r][c] = mul2(mul2(K[r][c], vr[c]), uf);
        }
        float2 pA0f[4], pArf[4];
        compute_pA(K, C2h, l, mate_src, pA0f, pArf);

        // K <- P * ex2(Mhn + pA)   (no gmin: P invariant to K scaling)
        #pragma unroll
        for (int r = 0; r < 9; r++) {
            const float2* pa = (r == 0 && l0) ? pA0f : pArf;
            #pragma unroll
            for (int c = 0; c < 4; c++) {
                float2 g = add2(Mh_s[r * 4 + c][tid], pa[c]);
                g.x = ex2(g.x); g.y = ex2(g.y);
                K[r][c] = mul2(K[r][c], g);
            }
        }
        #pragma unroll
        for (int c = 0; c < 4; c++) vr[c] = bc2(1.f);

        // Sinkhorn
        #pragma unroll 1
        for (int inner = 0; inner < 10; inner++) {
            #pragma unroll
            for (int r = 0; r < 9; r++) {
                float2 d = mul2(K[r][0], vr[0]);
                d = fma2(K[r][1], vr[1], d);
                d = fma2(K[r][2], vr[2], d);
                d = fma2(K[r][3], vr[3], d);
                u[r] = __fdividef(1.f / 17.f, d.x + d.y + 1e-30f);
            }
            #pragma unroll
            for (int c = 0; c < 4; c++) {
                float2 part = mul2(K[0][c], bc2(u[0]));
                #pragma unroll
                for (int r = 1; r < 9; r++)
                    part = fma2(K[r][c], bc2(u[r]), part);
                part.x += __shfl_xor_sync(FULLMASK, part.x, 1);
                part.y += __shfl_xor_sync(FULLMASK, part.y, 1);
                vr[c].x = __fdividef(0.125f, part.x + 1e-30f);
                vr[c].y = __fdividef(0.125f, part.y + 1e-30f);
            }
        }
    }

    // ---- Final: P in place, fgw = -(1/EKC) * sum((Mhn + pA) .* P) ----
    #pragma unroll
    for (int r = 0; r < 9; r++) {
        float2 uf = bc2(u[r]);
        #pragma unroll
        for (int c = 0; c < 4; c++) K[r][c] = mul2(mul2(K[r][c], vr[c]), uf);
    }
    {
        float2 pA0f[4], pArf[4];
        compute_pA(K, C2h, l, mate_src, pA0f, pArf);
        float2 accv = bc2(0.f);
        #pragma unroll
        for (int r = 0; r < 9; r++) {
            const float2* pa = (r == 0 && l0) ? pA0f : pArf;
            #pragma unroll
            for (int c = 0; c < 4; c++)
                accv = fma2(add2(Mh_s[r * 4 + c][tid], pa[c]), K[r][c], accv);
        }
        float loc = accv.x + accv.y;
        loc += __shfl_xor_sync(FULLMASK, loc, 1);
        if (l0) fgw_s[w][t] = loc * (-1.f / EKC);
    }
    __syncwarp();

    if (lane < 8) {
        float o = __ldg(&bvec[lane]);
        #pragma unroll
        for (int tt = 0; tt < 16; tt++)
            o += fgw_s[w][tt] * __ldg(&Wm[tt * 8 + lane]);
        out[node * 8 + lane] = o;
    }
}

extern "C" void kernel_launch(void* const* d_in, const int* in_sizes, int n_in,
                              void* d_out, int out_size) {
    const float* x   = (const float*)d_in[0];
    const int*   ei  = (const int*)d_in[1];
    const float* lt  = (const float*)d_in[2];
    const float* tf  = (const float*)d_in[3];
    const float* Wm  = (const float*)d_in[4];
    const float* bv  = (const float*)d_in[5];
    float* out = (float*)d_out;

    const int N = in_sizes[0] / 128;   // 10000 (even)
    const int* dst = ei + N * 16;

    precompute_kernel<<<(N + 31) / 32, 128>>>(x, lt, tf, N);
    otgnn_fgw_kernel<<<N / 2, 64>>>(dst, Wm, bv, out);
}

// round 8
// speedup vs baseline: 4.5574x; 1.0160x over previous
#include <cuda_runtime.h>

#define FULLMASK 0xffffffffu
#define MAXN 16384

// Scratch (device globals — no allocation)
__device__ float g_G[MAXN * 128];   // G[j][tm] = x_j . tf_{t,m}
__device__ float g_xn2[MAXN];       // |x_j|^2
__device__ float g_tf2[128];        // |tf_{t,m}|^2
__device__ float g_C2s[128 * 8];    // symmetrized C2 rows

// ---------------- packed f32x2 + MUFU helpers ----------------
union f2u { float2 f; unsigned long long u; };
__device__ __forceinline__ float2 fma2(float2 a, float2 b, float2 c) {
    f2u A, B, C, D; A.f = a; B.f = b; C.f = c;
    asm("fma.rn.f32x2 %0, %1, %2, %3;" : "=l"(D.u) : "l"(A.u), "l"(B.u), "l"(C.u));
    return D.f;
}
__device__ __forceinline__ float2 mul2(float2 a, float2 b) {
    f2u A, B, D; A.f = a; B.f = b;
    asm("mul.rn.f32x2 %0, %1, %2;" : "=l"(D.u) : "l"(A.u), "l"(B.u));
    return D.f;
}
__device__ __forceinline__ float2 add2(float2 a, float2 b) {
    f2u A, B, D; A.f = a; B.f = b;
    asm("add.rn.f32x2 %0, %1, %2;" : "=l"(D.u) : "l"(A.u), "l"(B.u));
    return D.f;
}
__device__ __forceinline__ float ex2(float x) {
    float r; asm("ex2.approx.f32 %0, %1;" : "=f"(r) : "f"(x)); return r;
}
__device__ __forceinline__ float rcpf(float x) {
    float r; asm("rcp.approx.f32 %0, %1;" : "=f"(r) : "f"(x)); return r;
}
__device__ __forceinline__ float2 bc2(float s) { return make_float2(s, s); }

// ---------------- Kernel A: precompute (32 nodes/block) ----------------
__global__ void __launch_bounds__(128)
precompute_kernel(const float* __restrict__ x,
                  const float* __restrict__ lt,
                  const float* __restrict__ tf,
                  int N)
{
    __shared__ float xs[32][128];
    const int tid = threadIdx.x;
    const int n0  = blockIdx.x * 32;

    #pragma unroll
    for (int j = 0; j < 32; j++)
        xs[j][tid] = (n0 + j < N) ? __ldg(&x[(n0 + j) * 128 + tid]) : 0.f;
    __syncthreads();

    const float4* tfr = (const float4*)(tf + tid * 128);
    float acc[32];
    #pragma unroll
    for (int j = 0; j < 32; j++) acc[j] = 0.f;
    float tf2a = 0.f;
    #pragma unroll 1
    for (int c4 = 0; c4 < 32; c4++) {
        float4 tv = __ldg(&tfr[c4]);
        tf2a += tv.x*tv.x + tv.y*tv.y + tv.z*tv.z + tv.w*tv.w;
        #pragma unroll
        for (int j = 0; j < 32; j++) {
            float4 v = *(const float4*)&xs[j][c4 * 4];
            acc[j] += v.x*tv.x + v.y*tv.y + v.z*tv.z + v.w*tv.w;
        }
    }
    #pragma unroll
    for (int j = 0; j < 32; j++)
        if (n0 + j < N) g_G[(n0 + j) * 128 + tid] = acc[j];

    const int jn = tid >> 2, off = (tid & 3) * 32;
    float s = 0.f;
    #pragma unroll
    for (int k = 0; k < 32; k++) { float v = xs[jn][off + k]; s += v * v; }
    s += __shfl_xor_sync(FULLMASK, s, 1);
    s += __shfl_xor_sync(FULLMASK, s, 2);
    if ((tid & 3) == 0 && n0 + jn < N) g_xn2[n0 + jn] = s;

    if (blockIdx.x == 0) {
        g_tf2[tid] = tf2a;
        const int t = tid >> 3, m = tid & 7;
        #pragma unroll
        for (int l = 0; l < 8; l++)
            g_C2s[tid * 8 + l] = 0.5f * (__ldg(&lt[(t * 8 + m) * 8 + l]) +
                                         __ldg(&lt[(t * 8 + l) * 8 + m]));
    }
}

// +EKC*A for the star graph, 2-lane groups, C2 from thread-private smem.
// K holds P. Outputs full 8-wide pA0f (row 0) and pArf (rows >= 1).
__device__ __forceinline__ void compute_pA(
    const float2 K[9][4], const float2 (*C2p)[64], int tid,
    int l, int mate_src,
    float2 pA0f[4], float2 pArf[4])
{
    float2 s2[4], p02[4];
    #pragma unroll
    for (int c = 0; c < 4; c++) {
        float2 a = (l == 0) ? bc2(0.f) : K[0][c];
        #pragma unroll
        for (int r = 1; r < 9; r++) a = add2(a, K[r][c]);
        a.x += __shfl_xor_sync(FULLMASK, a.x, 1);
        a.y += __shfl_xor_sync(FULLMASK, a.y, 1);
        s2[c] = a;
        p02[c].x = __shfl_sync(FULLMASK, K[0][c].x, mate_src);
        p02[c].y = __shfl_sync(FULLMASK, K[0][c].y, mate_src);
    }
    float osA[4], osP[4];
    #pragma unroll
    for (int j = 0; j < 4; j++) {
        float2 c2 = C2p[j * 4 + 0][tid];
        float2 aA = mul2(s2[0], c2);
        float2 aP = mul2(p02[0], c2);
        #pragma unroll
        for (int c = 1; c < 4; c++) {
            c2 = C2p[j * 4 + c][tid];
            aA = fma2(s2[c],  c2, aA);
            aP = fma2(p02[c], c2, aP);
        }
        osA[j] = aA.x + aA.y;
        osP[j] = aP.x + aP.y;
    }
    float2 oA0 = make_float2(osA[0], osA[1]), oA1 = make_float2(osA[2], osA[3]);
    float2 oP0 = make_float2(osP[0], osP[1]), oP1 = make_float2(osP[2], osP[3]);
    float2 mA0, mA1, mP0, mP1;
    mA0.x = __shfl_xor_sync(FULLMASK, oA0.x, 1); mA0.y = __shfl_xor_sync(FULLMASK, oA0.y, 1);
    mA1.x = __shfl_xor_sync(FULLMASK, oA1.x, 1); mA1.y = __shfl_xor_sync(FULLMASK, oA1.y, 1);
    mP0.x = __shfl_xor_sync(FULLMASK, oP0.x, 1); mP0.y = __shfl_xor_sync(FULLMASK, oP0.y, 1);
    mP1.x = __shfl_xor_sync(FULLMASK, oP1.x, 1); mP1.y = __shfl_xor_sync(FULLMASK, oP1.y, 1);
    bool li = (l != 0);
    pA0f[0] = li ? mA0 : oA0; pA0f[1] = li ? mA1 : oA1;
    pA0f[2] = li ? oA0 : mA0; pA0f[3] = li ? oA1 : mA1;
    pArf[0] = li ? mP0 : oP0; pArf[1] = li ? mP1 : oP1;
    pArf[2] = li ? oP0 : mP0; pArf[3] = li ? oP1 : mP1;
}

// ---------------- Kernel B: FGW, 2 lanes per (node,template) ----------------
__global__ void __launch_bounds__(64, 8)
otgnn_fgw_kernel(const int* __restrict__ dst,
                 const float* __restrict__ Wm,
                 const float* __restrict__ bvec,
                 float* __restrict__ out)
{
    __shared__ float2 eMh_s[36][64];  // ex2(Mhn), thread-private slots
    __shared__ float2 C2p[16][64];    // EKC-scaled C2 own rows, thread-private
    __shared__ int   idxs[2][17];
    __shared__ float xn2s[2][17];
    __shared__ float fgw_s[2][16];

    const int tid  = threadIdx.x;
    const int w    = tid >> 5;
    const int lane = tid & 31;
    const int node = blockIdx.x * 2 + w;
    const int t    = lane >> 1;
    const int l    = lane & 1;
    const int mate_src = lane & ~1;
    const bool l0 = (l == 0);

    if (lane < 17) {
        int id = lane ? __ldg(&dst[node * 16 + lane - 1]) : node;
        idxs[w][lane] = id;
        xn2s[w][lane] = g_xn2[id];
    }
    __syncwarp();

    const float EKC = 7.21347520444482f;   // 5 * log2(e)
    const float HF  = -0.5f * EKC;

    // Own C2 rows 4l..4l+3; cc2; scale by EKC; stash in smem
    {
        float2 C2h[4][4];
        #pragma unroll
        for (int j = 0; j < 4; j++) {
            const float4* p = (const float4*)&g_C2s[(t * 8 + 4 * l + j) * 8];
            float4 a = __ldg(&p[0]), b = __ldg(&p[1]);
            C2h[j][0] = make_float2(a.x, a.y); C2h[j][1] = make_float2(a.z, a.w);
            C2h[j][2] = make_float2(b.x, b.y); C2h[j][3] = make_float2(b.z, b.w);
        }
        float2 cc2f[4];
        #pragma unroll
        for (int c = 0; c < 4; c++) {
            float2 a = mul2(C2h[0][c], C2h[0][c]);
            a = fma2(C2h[1][c], C2h[1][c], a);
            a = fma2(C2h[2][c], C2h[2][c], a);
            a = fma2(C2h[3][c], C2h[3][c], a);
            a.x += __shfl_xor_sync(FULLMASK, a.x, 1);
            a.y += __shfl_xor_sync(FULLMASK, a.y, 1);
            cc2f[c] = make_float2(a.x * 0.125f, a.y * 0.125f);
        }
        #pragma unroll
        for (int j = 0; j < 4; j++)
            #pragma unroll
            for (int c = 0; c < 4; c++)
                C2p[j * 4 + c][tid] = mul2(C2h[j][c], bc2(EKC));

        // Build eMh = ex2(Mhn), Mhn = -(M + c1h + cc2) * 0.5 * EKC
        float2 tf2f[4];
        float4 ta = *(const float4*)&g_tf2[t * 8];
        float4 tb = *(const float4*)&g_tf2[t * 8 + 4];
        tf2f[0] = make_float2(ta.x, ta.y); tf2f[1] = make_float2(ta.z, ta.w);
        tf2f[2] = make_float2(tb.x, tb.y); tf2f[3] = make_float2(tb.z, tb.w);
        #pragma unroll
        for (int r = 0; r < 9; r++) {
            int row = (r < 8) ? 2 * r + l : 16;   // lane1 r=8 duplicates row16 (x0 later)
            int id = idxs[w][row];
            float n2 = xn2s[w][row];
            float4 g0 = __ldg((const float4*)&g_G[id * 128 + t * 8]);
            float4 g1 = __ldg((const float4*)&g_G[id * 128 + t * 8 + 4]);
            float gg[8] = {g0.x,g0.y,g0.z,g0.w,g1.x,g1.y,g1.z,g1.w};
            float c1h = (r == 0 && l0) ? (16.f / 17.f) : (1.f / 17.f);
            #pragma unroll
            for (int c = 0; c < 4; c++) {
                float mx = (n2 + tf2f[c].x - 2.f * gg[2*c])   * (1.f / 128.f);
                float my = (n2 + tf2f[c].y - 2.f * gg[2*c+1]) * (1.f / 128.f);
                eMh_s[r * 4 + c][tid] = make_float2(ex2((mx + c1h + cc2f[c].x) * HF),
                                                    ex2((my + c1h + cc2f[c].y) * HF));
            }
        }
    }

    // State
    float2 K[9][4], vr[4];
    float u[9];
    #pragma unroll
    for (int r = 0; r < 9; r++) {
        float init = (r == 8) ? (l0 ? 1.f / 136.f : 0.f) : (1.f / 136.f);
        #pragma unroll
        for (int c = 0; c < 4; c++) K[r][c] = bc2(init);
        u[r] = 1.f;
    }
    #pragma unroll
    for (int c = 0; c < 4; c++) vr[c] = bc2(1.f);

    #pragma unroll 1
    for (int outer = 0; outer < 5; outer++) {
        // P in place: K <- u * K * v   (u carries the 1/8 fold from prior outer)
        #pragma unroll
        for (int r = 0; r < 9; r++) {
            float2 uf = bc2(u[r]);
            #pragma unroll
            for (int c = 0; c < 4; c++) K[r][c] = mul2(mul2(K[r][c], vr[c]), uf);
        }
        float2 pA0f[4], pArf[4];
        compute_pA(K, C2p, tid, l, mate_src, pA0f, pArf);

        // Column scale absorbed into v-init; only row-0 ratio applied to K.
        #pragma unroll
        for (int c = 0; c < 4; c++) {
            float2 epr, rfx;
            epr.x = ex2(pArf[c].x);
            epr.y = ex2(pArf[c].y);
            rfx.x = ex2(pA0f[c].x - pArf[c].x);
            rfx.y = ex2(pA0f[c].y - pArf[c].y);
            if (!l0) rfx = bc2(1.f);
            K[0][c] = mul2(mul2(K[0][c], eMh_s[c][tid]), rfx);
            #pragma unroll
            for (int r = 1; r < 9; r++)
                K[r][c] = mul2(K[r][c], eMh_s[r * 4 + c][tid]);
            vr[c] = epr;
        }

        // Sinkhorn (raw reciprocals; constants telescope to 1/8)
        #pragma unroll 1
        for (int inner = 0; inner < 10; inner++) {
            #pragma unroll
            for (int r = 0; r < 9; r++) {
                float2 d = mul2(K[r][0], vr[0]);
                d = fma2(K[r][1], vr[1], d);
                d = fma2(K[r][2], vr[2], d);
                d = fma2(K[r][3], vr[3], d);
                u[r] = rcpf(d.x + d.y + 1e-30f);
            }
            #pragma unroll
            for (int c = 0; c < 4; c++) {
                float2 part = mul2(K[0][c], bc2(u[0]));
                #pragma unroll
                for (int r = 1; r < 9; r++)
                    part = fma2(K[r][c], bc2(u[r]), part);
                part.x += __shfl_xor_sync(FULLMASK, part.x, 1);
                part.y += __shfl_xor_sync(FULLMASK, part.y, 1);
                vr[c].x = rcpf(part.x + 1e-30f);
                vr[c].y = rcpf(part.y + 1e-30f);
            }
        }
        #pragma unroll
        for (int r = 0; r < 9; r++) u[r] *= 0.125f;
    }

    // ---- Final: P in place, recompute Mhn, fgw = -(1/EKC) sum((Mhn+pA).*P) ----
    #pragma unroll
    for (int r = 0; r < 9; r++) {
        float2 uf = bc2(u[r]);
        #pragma unroll
        for (int c = 0; c < 4; c++) K[r][c] = mul2(mul2(K[r][c], vr[c]), uf);
    }
    {
        float2 pA0f[4], pArf[4];
        compute_pA(K, C2p, tid, l, mate_src, pA0f, pArf);

        // cc2 from scaled C2p: (1/8)/EKC^2 * sum of squares
        float2 cc2f[4];
        const float CSC = 0.125f / (EKC * EKC);
        #pragma unroll
        for (int c = 0; c < 4; c++) {
            float2 a = mul2(C2p[c][tid], C2p[c][tid]);
            a = fma2(C2p[4 + c][tid],  C2p[4 + c][tid],  a);
            a = fma2(C2p[8 + c][tid],  C2p[8 + c][tid],  a);
            a = fma2(C2p[12 + c][tid], C2p[12 + c][tid], a);
            a.x += __shfl_xor_sync(FULLMASK, a.x, 1);
            a.y += __shfl_xor_sync(FULLMASK, a.y, 1);
            cc2f[c] = make_float2(a.x * CSC, a.y * CSC);
        }
        float2 tf2f[4];
        float4 ta = *(const float4*)&g_tf2[t * 8];
        float4 tb = *(const float4*)&g_tf2[t * 8 + 4];
        tf2f[0] = make_float2(ta.x, ta.y); tf2f[1] = make_float2(ta.z, ta.w);
        tf2f[2] = make_float2(tb.x, tb.y); tf2f[3] = make_float2(tb.z, tb.w);

        float2 accv = bc2(0.f);
        #pragma unroll
        for (int r = 0; r < 9; r++) {
            int row = (r < 8) ? 2 * r + l : 16;
            int id = idxs[w][row];
            float n2 = xn2s[w][row];
            float4 g0 = __ldg((const float4*)&g_G[id * 128 + t * 8]);
            float4 g1 = __ldg((const float4*)&g_G[id * 128 + t * 8 + 4]);
            float gg[8] = {g0.x,g0.y,g0.z,g0.w,g1.x,g1.y,g1.z,g1.w};
            float c1h = (r == 0 && l0) ? (16.f / 17.f) : (1.f / 17.f);
            const float2* pa = (r == 0 && l0) ? pA0f : pArf;
            #pragma unroll
            for (int c = 0; c < 4; c++) {
                float mx = (n2 + tf2f[c].x - 2.f * gg[2*c])   * (1.f / 128.f);
                float my = (n2 + tf2f[c].y - 2.f * gg[2*c+1]) * (1.f / 128.f);
                float2 g = make_float2((mx + c1h + cc2f[c].x) * HF + pa[c].x,
                                       (my + c1h + cc2f[c].y) * HF + pa[c].y);
                accv = fma2(g, K[r][c], accv);
            }
        }
        float loc = accv.x + accv.y;
        loc += __shfl_xor_sync(FULLMASK, loc, 1);
        if (l0) fgw_s[w][t] = loc * (-1.f / EKC);
    }
    __syncwarp();

    if (lane < 8) {
        float o = __ldg(&bvec[lane]);
        #pragma unroll
        for (int tt = 0; tt < 16; tt++)
            o += fgw_s[w][tt] * __ldg(&Wm[tt * 8 + lane]);
        out[node * 8 + lane] = o;
    }
}

extern "C" void kernel_launch(void* const* d_in, const int* in_sizes, int n_in,
                              void* d_out, int out_size) {
    const float* x   = (const float*)d_in[0];
    const int*   ei  = (const int*)d_in[1];
    const float* lt  = (const float*)d_in[2];
    const float* tf  = (const float*)d_in[3];
    const float* Wm  = (const float*)d_in[4];
    const float* bv  = (const float*)d_in[5];
    float* out = (float*)d_out;

    const int N = in_sizes[0] / 128;   // 10000 (even)
    const int* dst = ei + N * 16;

    precompute_kernel<<<(N + 31) / 32, 128>>>(x, lt, tf, N);
    otgnn_fgw_kernel<<<N / 2, 64>>>(dst, Wm, bv, out);
}